// round 2
// baseline (speedup 1.0000x reference)
#include <cuda_runtime.h>
#include <cuda_bf16.h>
#include <cstdint>

#define N_NODES   20000
#define N_INPUT   64
#define KMAX      12
#define NBITS     64
#define N_OUT     10
#define NBATCH    64
#define TSTEPS    128
#define LUTW      128         /* 4096 bits / 32 words */
#define DUMMY     20000
#define ST_SZ     20008
#define GRID_MAIN 148
#define TPB_MAIN  1024
#define MAX_NPW   5

// ---------------- device globals (scratch; no allocations allowed) ----------------
__device__ __align__(16) unsigned short g_adj[N_NODES * 16];   // lane-reversed packed adjacency
__device__ unsigned int  g_lut[N_NODES * LUTW];                // 10.24 MB bit-packed LUT
__device__ uint2         g_st[2][ST_SZ];                       // bit-packed states; slot 20000 = always-0 dummy
__device__ uint2         g_u[TSTEPS * 64];                     // input-layer bits u[t][j]
__device__ uint2         g_xb[NBATCH * TSTEPS];                // packed x bits [b][t]
__device__ uint2         g_wc[64];                             // packed w_in columns
__device__ volatile unsigned g_arr[256];                       // per-CTA arrival flags

// ---------------- preprocessing ----------------

__global__ void k_pack_x(const int* __restrict__ x) {
    int wid  = (blockIdx.x * blockDim.x + threadIdx.x) >> 5;
    int lane = threadIdx.x & 31;
    if (wid >= NBATCH * TSTEPS) return;
    int b = wid >> 7, t = wid & 127;
    const int* p = x + ((size_t)b * TSTEPS + t) * NBITS;
    unsigned lo = __ballot_sync(0xffffffffu, p[lane] != 0);
    unsigned hi = __ballot_sync(0xffffffffu, p[lane + 32] != 0);
    if (lane == 0) g_xb[b * TSTEPS + t] = make_uint2(lo, hi);
}

__global__ void k_pack_w(const int* __restrict__ w_in) {
    int wid  = (blockIdx.x * blockDim.x + threadIdx.x) >> 5;
    int lane = threadIdx.x & 31;
    if (wid >= 64) return;
    unsigned lo = __ballot_sync(0xffffffffu, w_in[lane * 64 + wid] != 0);
    unsigned hi = __ballot_sync(0xffffffffu, w_in[(lane + 32) * 64 + wid] != 0);
    if (lane == 0) g_wc[wid] = make_uint2(lo, hi);
}

// u[t][j] bit b = ((x_bits[b][t] & w_col[j]) != 0)
__global__ void k_build_u() {
    int wid  = (blockIdx.x * blockDim.x + threadIdx.x) >> 5;
    int lane = threadIdx.x & 31;
    if (wid >= TSTEPS * 64) return;
    int t = wid >> 6, j = wid & 63;
    uint2 wc = g_wc[j];
    uint2 xa = g_xb[lane * TSTEPS + t];
    uint2 xb = g_xb[(lane + 32) * TSTEPS + t];
    unsigned lo = __ballot_sync(0xffffffffu, ((xa.x & wc.x) | (xa.y & wc.y)) != 0);
    unsigned hi = __ballot_sync(0xffffffffu, ((xb.x & wc.x) | (xb.y & wc.y)) != 0);
    if (lane == 0) g_u[t * 64 + j] = make_uint2(lo, hi);
}

// Fold adj_mask into adjacency, LANE-REVERSED: lane l = neighbor (11-l), so the
// butterfly transpose's output low 12 bits equal the LUT index with the
// reference's MSB-first power ordering. Masked -> DUMMY (state always 0);
// no-neighbor nodes -> self at neighbor slot 11 == lane 0 (weight 1).
__global__ void k_pack_adj(const int* __restrict__ adj_list, const int* __restrict__ adj_mask) {
    int n = blockIdx.x * blockDim.x + threadIdx.x;
    if (n >= N_NODES) return;
    unsigned a[12];
    int any = 0;
#pragma unroll
    for (int k = 0; k < KMAX; k++) {
        int m = adj_mask[n * KMAX + k];
        any |= m;
        a[k] = m ? (unsigned)adj_list[n * KMAX + k] : (unsigned)DUMMY;
    }
    if (!any) {
#pragma unroll
        for (int k = 0; k < KMAX; k++) a[k] = DUMMY;
        a[11] = (unsigned)n;   // idx = old state bit (identity LUT)
    }
    unsigned r[16];
#pragma unroll
    for (int l = 0; l < 12; l++) r[l] = a[11 - l];
    r[12] = r[13] = r[14] = r[15] = DUMMY;
    uint4 v0, v1;
    v0.x = r[0]  | (r[1]  << 16); v0.y = r[2]  | (r[3]  << 16);
    v0.z = r[4]  | (r[5]  << 16); v0.w = r[6]  | (r[7]  << 16);
    v1.x = r[8]  | (r[9]  << 16); v1.y = r[10] | (r[11] << 16);
    v1.z = r[12] | (r[13] << 16); v1.w = r[14] | (r[15] << 16);
    ((uint4*)g_adj)[n * 2]     = v0;
    ((uint4*)g_adj)[n * 2 + 1] = v1;
}

// Bit-pack the LUT. For no-neighbor nodes write the identity LUT (word0 = 0b10).
__global__ void k_pack_lut(const int* __restrict__ lut, const int* __restrict__ adj_mask) {
    int wid  = (blockIdx.x * blockDim.x + threadIdx.x) >> 5;
    int lane = threadIdx.x & 31;
    if (wid >= N_NODES * LUTW) return;
    int node = wid >> 7, wofs = wid & 127;
    int mv = (lane < KMAX) ? adj_mask[node * KMAX + lane] : 0;
    unsigned anym = __ballot_sync(0xffffffffu, mv != 0);
    unsigned word;
    if (anym == 0) {
        word = (wofs == 0) ? 2u : 0u;
    } else {
        int v = lut[(size_t)node * 4096 + (size_t)wofs * 32 + lane];
        word = __ballot_sync(0xffffffffu, v != 0);
    }
    if (lane == 0) g_lut[node * LUTW + wofs] = word;
}

__global__ void k_init(const int* __restrict__ init_states) {
    int i = blockIdx.x * blockDim.x + threadIdx.x;
    if (i < 256) g_arr[i] = 0;
    if (i >= ST_SZ) return;
    if (i < N_INPUT) {
        g_st[0][i] = g_u[i];                       // u[0][i]
    } else if (i < N_NODES) {
        int s = init_states[i];
        g_st[0][i] = s ? make_uint2(0xffffffffu, 0xffffffffu) : make_uint2(0u, 0u);
    } else {                                        // dummy + pad: zero both buffers
        g_st[0][i] = make_uint2(0u, 0u);
        g_st[1][i] = make_uint2(0u, 0u);
    }
}

// ---------------- main persistent kernel ----------------

// 32x32 bit-matrix transpose distributed across a warp (5 butterfly stages).
// In: lane l holds row l (bit j = col j). Out: lane j holds column j.
__device__ __forceinline__ unsigned btrans32(unsigned x, int lane) {
    unsigned y;
    y = __shfl_xor_sync(0xffffffffu, x, 16);
    x = (lane & 16) ? ((x & 0xffff0000u) | ((y & 0xffff0000u) >> 16))
                    : ((x & 0x0000ffffu) | ((y & 0x0000ffffu) << 16));
    y = __shfl_xor_sync(0xffffffffu, x, 8);
    x = (lane & 8)  ? ((x & 0xff00ff00u) | ((y & 0xff00ff00u) >> 8))
                    : ((x & 0x00ff00ffu) | ((y & 0x00ff00ffu) << 8));
    y = __shfl_xor_sync(0xffffffffu, x, 4);
    x = (lane & 4)  ? ((x & 0xf0f0f0f0u) | ((y & 0xf0f0f0f0u) >> 4))
                    : ((x & 0x0f0f0f0fu) | ((y & 0x0f0f0f0fu) << 4));
    y = __shfl_xor_sync(0xffffffffu, x, 2);
    x = (lane & 2)  ? ((x & 0xccccccccu) | ((y & 0xccccccccu) >> 2))
                    : ((x & 0x33333333u) | ((y & 0x33333333u) << 2));
    y = __shfl_xor_sync(0xffffffffu, x, 1);
    x = (lane & 1)  ? ((x & 0xaaaaaaaau) | ((y & 0xaaaaaaaau) >> 1))
                    : ((x & 0x55555555u) | ((y & 0x55555555u) << 1));
    return x;
}

// Flag-array grid barrier: no atomics; each CTA publishes its own step counter,
// threads i < nblocks poll flag i in parallel (one 128B line per warp).
__device__ __forceinline__ void grid_bar(int t, int nblocks) {
    __syncthreads();
    if (threadIdx.x == 0) {
        __threadfence();                           // release this CTA's state writes
        g_arr[blockIdx.x] = (unsigned)(t + 1);
    }
    if (threadIdx.x < nblocks) {
        while (g_arr[threadIdx.x] < (unsigned)(t + 1)) { }
    }
    __syncthreads();
}

__global__ void __launch_bounds__(TPB_MAIN, 1) k_main() {
    const int lane = threadIdx.x & 31;
    const int gw   = blockIdx.x * (TPB_MAIN / 32) + (threadIdx.x >> 5);
    const int NW   = gridDim.x * (TPB_MAIN / 32);
    const int nb   = gridDim.x;

    // hoist per-warp constants: node ids, lane-reversed adjacency, LUT row offsets
    int nodes[MAX_NPW];
    unsigned adjs[MAX_NPW];
    unsigned lutoff[MAX_NPW];
    bool valid[MAX_NPW];
#pragma unroll
    for (int i = 0; i < MAX_NPW; i++) {
        int node = N_INPUT + gw + i * NW;
        valid[i]  = node < N_NODES;
        nodes[i]  = valid[i] ? node : N_INPUT;
        adjs[i]   = valid[i] ? (unsigned)g_adj[nodes[i] * 16 + ((lane < 16) ? lane : 15)]
                             : (unsigned)DUMMY;
        lutoff[i] = (unsigned)nodes[i] * LUTW;
    }

    int cur = 0;
    for (int t = 0; t < TSTEPS; t++) {
        const uint2* __restrict__ S = g_st[cur];
        uint2* __restrict__ D = g_st[cur ^ 1];

        // stage next step's input-layer bits into the destination buffer
        if (gw < 2 && t + 1 < TSTEPS) {
            int j = gw * 32 + lane;
            D[j] = g_u[(t + 1) * 64 + j];
        }

        // front-batch all gathers (L2-coherent; L1 may be stale across steps)
        uint2 w[MAX_NPW];
#pragma unroll
        for (int i = 0; i < MAX_NPW; i++)
            w[i] = __ldcg(&S[adjs[i]]);

#pragma unroll
        for (int i = 0; i < MAX_NPW; i++) {
            if (!valid[i]) continue;
            unsigned iL = btrans32(w[i].x, lane);   // lane j: 12-bit idx for batch j
            unsigned iH = btrans32(w[i].y, lane);   // lane j: idx for batch 32+j
            unsigned bl = (__ldg(&g_lut[lutoff[i] + (iL >> 5)]) >> (iL & 31)) & 1u;
            unsigned bh = (__ldg(&g_lut[lutoff[i] + (iH >> 5)]) >> (iH & 31)) & 1u;
            unsigned nlo = __ballot_sync(0xffffffffu, bl);
            unsigned nhi = __ballot_sync(0xffffffffu, bh);
            if (lane == 0) D[nodes[i]] = make_uint2(nlo, nhi);
        }

        grid_bar(t, nb);
        cur ^= 1;
    }
}

// ---------------- readout: sigmoid(states[:,64:] @ W^T + b) ----------------

__global__ void k_readout(const float* __restrict__ W, const float* __restrict__ bias,
                          float* __restrict__ out) {
    int b   = blockIdx.x;        // 64 blocks
    int tid = threadIdx.x;       // 256 threads
    int lane = tid & 31, wrp = tid >> 5;
    const uint2* __restrict__ S = g_st[0];   // TSTEPS even -> final states in buffer 0

    float acc[N_OUT];
#pragma unroll
    for (int o = 0; o < N_OUT; o++) acc[o] = 0.f;

    const int bsh = b & 31;
    for (int n = N_INPUT + tid; n < N_NODES; n += blockDim.x) {
        uint2 w = S[n];
        unsigned word = (b < 32) ? w.x : w.y;
        float bit = (float)((word >> bsh) & 1u);
        const float* wp = W + (n - N_INPUT);
#pragma unroll
        for (int o = 0; o < N_OUT; o++)
            acc[o] += bit * wp[o * (N_NODES - N_INPUT)];
    }

    __shared__ float part[8][N_OUT];
#pragma unroll
    for (int o = 0; o < N_OUT; o++) {
        float v = acc[o];
#pragma unroll
        for (int off = 16; off; off >>= 1) v += __shfl_down_sync(0xffffffffu, v, off);
        if (lane == 0) part[wrp][o] = v;
    }
    __syncthreads();
    if (tid < N_OUT) {
        float s = bias[tid];
#pragma unroll
        for (int w2 = 0; w2 < 8; w2++) s += part[w2][tid];
        out[b * N_OUT + tid] = 1.0f / (1.0f + expf(-s));
    }
}

// ---------------- launch ----------------

extern "C" void kernel_launch(void* const* d_in, const int* in_sizes, int n_in,
                              void* d_out, int out_size) {
    (void)in_sizes; (void)n_in; (void)out_size;
    const int*   x           = (const int*)d_in[0];
    const int*   w_in        = (const int*)d_in[1];
    const int*   adj_list    = (const int*)d_in[2];
    const int*   adj_mask    = (const int*)d_in[3];
    const int*   lut         = (const int*)d_in[4];
    const int*   init_states = (const int*)d_in[5];
    const float* W_out       = (const float*)d_in[6];
    const float* b_out       = (const float*)d_in[7];
    float* out = (float*)d_out;

    k_pack_x<<<(NBATCH * TSTEPS * 32) / 256, 256>>>(x);
    k_pack_w<<<8, 256>>>(w_in);
    k_build_u<<<(TSTEPS * 64 * 32) / 256, 256>>>();
    k_pack_adj<<<(N_NODES + 255) / 256, 256>>>(adj_list, adj_mask);
    k_pack_lut<<<(N_NODES * LUTW) / 8, 256>>>(lut, adj_mask);
    k_init<<<(ST_SZ + 255) / 256, 256>>>(init_states);

    int dev = 0, sms = GRID_MAIN;
    cudaGetDevice(&dev);
    cudaDeviceGetAttribute(&sms, cudaDevAttrMultiProcessorCount, dev);
    int grid = (sms < GRID_MAIN) ? sms : GRID_MAIN;   // wave-1 co-residency guaranteed

    k_main<<<grid, TPB_MAIN>>>();
    k_readout<<<NBATCH, 256>>>(W_out, b_out, out);
}

// round 3
// speedup vs baseline: 1.1477x; 1.1477x over previous
#include <cuda_runtime.h>
#include <cuda_bf16.h>
#include <cstdint>

#define N_NODES   20000
#define N_INPUT   64
#define KMAX      12
#define NBITS     64
#define N_OUT     10
#define NBATCH    64
#define TSTEPS    128
#define LUTW      128         /* 4096 bits / 32 words */
#define DUMMY     20000
#define ST_SZ     20008
#define GRID_MAIN 148
#define TPB_MAIN  512
#define MAX_NPW   9           /* ceil(19936 / (148*16)) */

// ---------------- device globals (scratch; no allocations allowed) ----------------
__device__ __align__(16) unsigned short g_adj[N_NODES * 16];   // lane-reversed packed adjacency
__device__ unsigned int  g_lut[N_NODES * LUTW];                // 10.24 MB bit-packed LUT
__device__ uint2         g_st[2][ST_SZ];                       // bit-packed states; slot 20000 = always-0 dummy
__device__ uint2         g_u[TSTEPS * 64];                     // input-layer bits u[t][j]
__device__ uint2         g_xb[NBATCH * TSTEPS];                // packed x bits [b][t]
__device__ uint2         g_wc[64];                             // packed w_in columns
__device__ volatile unsigned g_arr[256];                       // per-CTA arrival flags

// ---------------- preprocessing ----------------

__global__ void k_pack_x(const int* __restrict__ x) {
    int wid  = (blockIdx.x * blockDim.x + threadIdx.x) >> 5;
    int lane = threadIdx.x & 31;
    if (wid >= NBATCH * TSTEPS) return;
    int b = wid >> 7, t = wid & 127;
    const int* p = x + ((size_t)b * TSTEPS + t) * NBITS;
    unsigned lo = __ballot_sync(0xffffffffu, p[lane] != 0);
    unsigned hi = __ballot_sync(0xffffffffu, p[lane + 32] != 0);
    if (lane == 0) g_xb[b * TSTEPS + t] = make_uint2(lo, hi);
}

__global__ void k_pack_w(const int* __restrict__ w_in) {
    int wid  = (blockIdx.x * blockDim.x + threadIdx.x) >> 5;
    int lane = threadIdx.x & 31;
    if (wid >= 64) return;
    unsigned lo = __ballot_sync(0xffffffffu, w_in[lane * 64 + wid] != 0);
    unsigned hi = __ballot_sync(0xffffffffu, w_in[(lane + 32) * 64 + wid] != 0);
    if (lane == 0) g_wc[wid] = make_uint2(lo, hi);
}

// u[t][j] bit b = ((x_bits[b][t] & w_col[j]) != 0)
__global__ void k_build_u() {
    int wid  = (blockIdx.x * blockDim.x + threadIdx.x) >> 5;
    int lane = threadIdx.x & 31;
    if (wid >= TSTEPS * 64) return;
    int t = wid >> 6, j = wid & 63;
    uint2 wc = g_wc[j];
    uint2 xa = g_xb[lane * TSTEPS + t];
    uint2 xb = g_xb[(lane + 32) * TSTEPS + t];
    unsigned lo = __ballot_sync(0xffffffffu, ((xa.x & wc.x) | (xa.y & wc.y)) != 0);
    unsigned hi = __ballot_sync(0xffffffffu, ((xb.x & wc.x) | (xb.y & wc.y)) != 0);
    if (lane == 0) g_u[t * 64 + j] = make_uint2(lo, hi);
}

// Fold adj_mask into adjacency, LANE-REVERSED: lane l = neighbor (11-l), so the
// butterfly transpose's output low 12 bits equal the LUT index with the
// reference's MSB-first power ordering. Masked -> DUMMY (state always 0);
// no-neighbor nodes -> self at neighbor slot 11 == lane 0 (weight 1).
__global__ void k_pack_adj(const int* __restrict__ adj_list, const int* __restrict__ adj_mask) {
    int n = blockIdx.x * blockDim.x + threadIdx.x;
    if (n >= N_NODES) return;
    unsigned a[12];
    int any = 0;
#pragma unroll
    for (int k = 0; k < KMAX; k++) {
        int m = adj_mask[n * KMAX + k];
        any |= m;
        a[k] = m ? (unsigned)adj_list[n * KMAX + k] : (unsigned)DUMMY;
    }
    if (!any) {
#pragma unroll
        for (int k = 0; k < KMAX; k++) a[k] = DUMMY;
        a[11] = (unsigned)n;   // idx = old state bit (identity LUT)
    }
    unsigned r[16];
#pragma unroll
    for (int l = 0; l < 12; l++) r[l] = a[11 - l];
    r[12] = r[13] = r[14] = r[15] = DUMMY;
    uint4 v0, v1;
    v0.x = r[0]  | (r[1]  << 16); v0.y = r[2]  | (r[3]  << 16);
    v0.z = r[4]  | (r[5]  << 16); v0.w = r[6]  | (r[7]  << 16);
    v1.x = r[8]  | (r[9]  << 16); v1.y = r[10] | (r[11] << 16);
    v1.z = r[12] | (r[13] << 16); v1.w = r[14] | (r[15] << 16);
    ((uint4*)g_adj)[n * 2]     = v0;
    ((uint4*)g_adj)[n * 2 + 1] = v1;
}

// Bit-pack the LUT. For no-neighbor nodes write the identity LUT (word0 = 0b10).
__global__ void k_pack_lut(const int* __restrict__ lut, const int* __restrict__ adj_mask) {
    int wid  = (blockIdx.x * blockDim.x + threadIdx.x) >> 5;
    int lane = threadIdx.x & 31;
    if (wid >= N_NODES * LUTW) return;
    int node = wid >> 7, wofs = wid & 127;
    int mv = (lane < KMAX) ? adj_mask[node * KMAX + lane] : 0;
    unsigned anym = __ballot_sync(0xffffffffu, mv != 0);
    unsigned word;
    if (anym == 0) {
        word = (wofs == 0) ? 2u : 0u;
    } else {
        int v = lut[(size_t)node * 4096 + (size_t)wofs * 32 + lane];
        word = __ballot_sync(0xffffffffu, v != 0);
    }
    if (lane == 0) g_lut[node * LUTW + wofs] = word;
}

__global__ void k_init(const int* __restrict__ init_states) {
    int i = blockIdx.x * blockDim.x + threadIdx.x;
    if (i < 256) g_arr[i] = 0;
    if (i >= ST_SZ) return;
    if (i < N_INPUT) {
        g_st[0][i] = g_u[i];                       // u[0][i]
    } else if (i < N_NODES) {
        int s = init_states[i];
        g_st[0][i] = s ? make_uint2(0xffffffffu, 0xffffffffu) : make_uint2(0u, 0u);
    } else {                                        // dummy + pad: zero both buffers
        g_st[0][i] = make_uint2(0u, 0u);
        g_st[1][i] = make_uint2(0u, 0u);
    }
}

// ---------------- main persistent kernel ----------------

// 32x32 bit-matrix transpose distributed across a warp (5 butterfly stages).
// In: lane l holds row l (bit j = col j). Out: lane j holds column j.
__device__ __forceinline__ unsigned btrans32(unsigned x, int lane) {
    unsigned y;
    y = __shfl_xor_sync(0xffffffffu, x, 16);
    x = (lane & 16) ? ((x & 0xffff0000u) | ((y & 0xffff0000u) >> 16))
                    : ((x & 0x0000ffffu) | ((y & 0x0000ffffu) << 16));
    y = __shfl_xor_sync(0xffffffffu, x, 8);
    x = (lane & 8)  ? ((x & 0xff00ff00u) | ((y & 0xff00ff00u) >> 8))
                    : ((x & 0x00ff00ffu) | ((y & 0x00ff00ffu) << 8));
    y = __shfl_xor_sync(0xffffffffu, x, 4);
    x = (lane & 4)  ? ((x & 0xf0f0f0f0u) | ((y & 0xf0f0f0f0u) >> 4))
                    : ((x & 0x0f0f0f0fu) | ((y & 0x0f0f0f0fu) << 4));
    y = __shfl_xor_sync(0xffffffffu, x, 2);
    x = (lane & 2)  ? ((x & 0xccccccccu) | ((y & 0xccccccccu) >> 2))
                    : ((x & 0x33333333u) | ((y & 0x33333333u) << 2));
    y = __shfl_xor_sync(0xffffffffu, x, 1);
    x = (lane & 1)  ? ((x & 0xaaaaaaaau) | ((y & 0xaaaaaaaau) >> 1))
                    : ((x & 0x55555555u) | ((y & 0x55555555u) << 1));
    return x;
}

// Flag-array grid barrier: each CTA publishes its own step counter (no atomics);
// only warp 0 polls, covering all flags with a 32-lane stride + __all_sync.
__device__ __forceinline__ void grid_bar(int t, int nb) {
    __syncthreads();
    if (threadIdx.x == 0) {
        __threadfence();                           // release this CTA's state writes
        g_arr[blockIdx.x] = (unsigned)(t + 1);
    }
    if (threadIdx.x < 32) {
        bool ok;
        do {
            ok = true;
            for (int f = (int)threadIdx.x; f < nb; f += 32)
                ok &= (g_arr[f] >= (unsigned)(t + 1));
        } while (!__all_sync(0xffffffffu, ok));
        __threadfence();
    }
    __syncthreads();
}

__global__ void __launch_bounds__(TPB_MAIN, 1) k_main() {
    const int lane = threadIdx.x & 31;
    const int gw   = blockIdx.x * (TPB_MAIN / 32) + (threadIdx.x >> 5);
    const int NW   = gridDim.x * (TPB_MAIN / 32);
    const int nb   = gridDim.x;
    const int lsel = (lane < 16) ? lane : 15;
    const int node0 = N_INPUT + gw;

    // hoist lane-reversed adjacency into registers (constant across all steps)
    unsigned adjreg[MAX_NPW];
    int npw = 0;
#pragma unroll
    for (int i = 0; i < MAX_NPW; i++) {
        int n = node0 + i * NW;
        bool v = n < N_NODES;
        adjreg[i] = v ? (unsigned)g_adj[n * 16 + lsel] : (unsigned)DUMMY;
        if (v) npw = i + 1;
    }

    int cur = 0;
    for (int t = 0; t < TSTEPS; t++) {
        const uint2* __restrict__ S = g_st[cur];
        uint2* __restrict__ D = g_st[cur ^ 1];

        // stage next step's input-layer bits into the destination buffer
        if (gw < 2 && t + 1 < TSTEPS) {
            int j = gw * 32 + lane;
            D[j] = g_u[(t + 1) * 64 + j];
        }

        // depth-1 software pipeline: prefetch next gather while computing current
        uint2 wn = __ldcg(&S[adjreg[0]]);       // L2-coherent (L1 stale across steps)
        int node = node0;
#pragma unroll
        for (int i = 0; i < MAX_NPW; i++) {
            if (i >= npw) break;
            uint2 w = wn;
            if (i + 1 < MAX_NPW) wn = __ldcg(&S[adjreg[i + 1]]);   // DUMMY-safe
            unsigned iL = btrans32(w.x, lane);  // lane j: 12-bit LUT idx for batch j
            unsigned iH = btrans32(w.y, lane);  // lane j: idx for batch 32+j
            const unsigned* __restrict__ row = g_lut + (unsigned)node * LUTW;
            unsigned bl = (__ldg(&row[iL >> 5]) >> (iL & 31)) & 1u;
            unsigned bh = (__ldg(&row[iH >> 5]) >> (iH & 31)) & 1u;
            unsigned nlo = __ballot_sync(0xffffffffu, bl);
            unsigned nhi = __ballot_sync(0xffffffffu, bh);
            if (lane == 0) D[node] = make_uint2(nlo, nhi);
            node += NW;
        }

        grid_bar(t, nb);
        cur ^= 1;
    }
}

// ---------------- readout: sigmoid(states[:,64:] @ W^T + b) ----------------

__global__ void k_readout(const float* __restrict__ W, const float* __restrict__ bias,
                          float* __restrict__ out) {
    int b   = blockIdx.x;        // 64 blocks
    int tid = threadIdx.x;       // 256 threads
    int lane = tid & 31, wrp = tid >> 5;
    const uint2* __restrict__ S = g_st[0];   // TSTEPS even -> final states in buffer 0

    float acc[N_OUT];
#pragma unroll
    for (int o = 0; o < N_OUT; o++) acc[o] = 0.f;

    const int bsh = b & 31;
    for (int n = N_INPUT + tid; n < N_NODES; n += blockDim.x) {
        uint2 w = S[n];
        unsigned word = (b < 32) ? w.x : w.y;
        float bit = (float)((word >> bsh) & 1u);
        const float* wp = W + (n - N_INPUT);
#pragma unroll
        for (int o = 0; o < N_OUT; o++)
            acc[o] += bit * wp[o * (N_NODES - N_INPUT)];
    }

    __shared__ float part[8][N_OUT];
#pragma unroll
    for (int o = 0; o < N_OUT; o++) {
        float v = acc[o];
#pragma unroll
        for (int off = 16; off; off >>= 1) v += __shfl_down_sync(0xffffffffu, v, off);
        if (lane == 0) part[wrp][o] = v;
    }
    __syncthreads();
    if (tid < N_OUT) {
        float s = bias[tid];
#pragma unroll
        for (int w2 = 0; w2 < 8; w2++) s += part[w2][tid];
        out[b * N_OUT + tid] = 1.0f / (1.0f + expf(-s));
    }
}

// ---------------- launch ----------------

extern "C" void kernel_launch(void* const* d_in, const int* in_sizes, int n_in,
                              void* d_out, int out_size) {
    (void)in_sizes; (void)n_in; (void)out_size;
    const int*   x           = (const int*)d_in[0];
    const int*   w_in        = (const int*)d_in[1];
    const int*   adj_list    = (const int*)d_in[2];
    const int*   adj_mask    = (const int*)d_in[3];
    const int*   lut         = (const int*)d_in[4];
    const int*   init_states = (const int*)d_in[5];
    const float* W_out       = (const float*)d_in[6];
    const float* b_out       = (const float*)d_in[7];
    float* out = (float*)d_out;

    k_pack_x<<<(NBATCH * TSTEPS * 32) / 256, 256>>>(x);
    k_pack_w<<<8, 256>>>(w_in);
    k_build_u<<<(TSTEPS * 64 * 32) / 256, 256>>>();
    k_pack_adj<<<(N_NODES + 255) / 256, 256>>>(adj_list, adj_mask);
    k_pack_lut<<<(N_NODES * LUTW) / 8, 256>>>(lut, adj_mask);
    k_init<<<(ST_SZ + 255) / 256, 256>>>(init_states);

    int dev = 0, sms = GRID_MAIN;
    cudaGetDevice(&dev);
    cudaDeviceGetAttribute(&sms, cudaDevAttrMultiProcessorCount, dev);
    int grid = (sms < GRID_MAIN) ? sms : GRID_MAIN;   // wave-1 co-residency guaranteed

    k_main<<<grid, TPB_MAIN>>>();
    k_readout<<<NBATCH, 256>>>(W_out, b_out, out);
}

// round 4
// speedup vs baseline: 1.6531x; 1.4404x over previous
#include <cuda_runtime.h>
#include <cuda_bf16.h>
#include <cstdint>

#define N_NODES   20000
#define N_INPUT   64
#define KMAX      12
#define NBITS     64
#define N_OUT     10
#define NBATCH    64
#define TSTEPS    128
#define LUTW      128         /* 4096 bits / 32 words */
#define DUMMY     20000
#define ST_SZ     20008
#define GRID_MAIN 148
#define TPB_MAIN  1024

// ---------------- device globals (scratch; no allocations allowed) ----------------
__device__ __align__(16) unsigned short g_adj[N_NODES * 16];   // lane-reversed packed adjacency
__device__ unsigned int  g_lut[N_NODES * LUTW];                // 10.24 MB bit-packed LUT
__device__ unsigned char g_non[N_NODES];                       // no-neighbor flag per node
__device__ uint2         g_st[2][ST_SZ];                       // bit-packed states; slot 20000 = always-0 dummy
__device__ uint2         g_u[TSTEPS * 64];                     // input-layer bits u[t][j]
__device__ uint2         g_xb[NBATCH * TSTEPS];                // packed x bits [b][t]
__device__ uint2         g_wc[64];                             // packed w_in columns
__device__ unsigned int  g_arrive;
__device__ volatile unsigned int g_gen;

// ---------------- preprocessing ----------------

__global__ void k_pack_x(const int* __restrict__ x) {
    int wid  = (blockIdx.x * blockDim.x + threadIdx.x) >> 5;
    int lane = threadIdx.x & 31;
    if (wid >= NBATCH * TSTEPS) return;
    int b = wid >> 7, t = wid & 127;
    const int* p = x + ((size_t)b * TSTEPS + t) * NBITS;
    unsigned lo = __ballot_sync(0xffffffffu, p[lane] != 0);
    unsigned hi = __ballot_sync(0xffffffffu, p[lane + 32] != 0);
    if (lane == 0) g_xb[b * TSTEPS + t] = make_uint2(lo, hi);
}

__global__ void k_pack_w(const int* __restrict__ w_in) {
    int wid  = (blockIdx.x * blockDim.x + threadIdx.x) >> 5;
    int lane = threadIdx.x & 31;
    if (wid >= 64) return;
    unsigned lo = __ballot_sync(0xffffffffu, w_in[lane * 64 + wid] != 0);
    unsigned hi = __ballot_sync(0xffffffffu, w_in[(lane + 32) * 64 + wid] != 0);
    if (lane == 0) g_wc[wid] = make_uint2(lo, hi);
}

// u[t][j] bit b = ((x_bits[b][t] & w_col[j]) != 0)
__global__ void k_build_u() {
    int wid  = (blockIdx.x * blockDim.x + threadIdx.x) >> 5;
    int lane = threadIdx.x & 31;
    if (wid >= TSTEPS * 64) return;
    int t = wid >> 6, j = wid & 63;
    uint2 wc = g_wc[j];
    uint2 xa = g_xb[lane * TSTEPS + t];
    uint2 xb = g_xb[(lane + 32) * TSTEPS + t];
    unsigned lo = __ballot_sync(0xffffffffu, ((xa.x & wc.x) | (xa.y & wc.y)) != 0);
    unsigned hi = __ballot_sync(0xffffffffu, ((xb.x & wc.x) | (xb.y & wc.y)) != 0);
    if (lane == 0) g_u[t * 64 + j] = make_uint2(lo, hi);
}

// Fold adj_mask into adjacency, LANE-REVERSED: lane l = neighbor (11-l), so the
// butterfly transpose's output low 12 bits equal the LUT index with the
// reference's MSB-first power ordering. Masked -> DUMMY (state always 0);
// no-neighbor nodes -> self at neighbor slot 11 == lane 0. Also records the
// no-neighbor flag so k_pack_lut does not have to re-read adj_mask (123MB saved).
__global__ void k_pack_adj(const int* __restrict__ adj_list, const int* __restrict__ adj_mask) {
    int n = blockIdx.x * blockDim.x + threadIdx.x;
    if (n >= N_NODES) return;
    unsigned a[12];
    int any = 0;
#pragma unroll
    for (int k = 0; k < KMAX; k++) {
        int m = adj_mask[n * KMAX + k];
        any |= m;
        a[k] = m ? (unsigned)adj_list[n * KMAX + k] : (unsigned)DUMMY;
    }
    if (!any) {
#pragma unroll
        for (int k = 0; k < KMAX; k++) a[k] = DUMMY;
        a[11] = (unsigned)n;   // idx = old state bit (identity LUT)
    }
    g_non[n] = (unsigned char)(!any);
    unsigned r[16];
#pragma unroll
    for (int l = 0; l < 12; l++) r[l] = a[11 - l];
    r[12] = r[13] = r[14] = r[15] = DUMMY;
    uint4 v0, v1;
    v0.x = r[0]  | (r[1]  << 16); v0.y = r[2]  | (r[3]  << 16);
    v0.z = r[4]  | (r[5]  << 16); v0.w = r[6]  | (r[7]  << 16);
    v1.x = r[8]  | (r[9]  << 16); v1.y = r[10] | (r[11] << 16);
    v1.z = r[12] | (r[13] << 16); v1.w = r[14] | (r[15] << 16);
    ((uint4*)g_adj)[n * 2]     = v0;
    ((uint4*)g_adj)[n * 2 + 1] = v1;
}

// Bit-pack the LUT. For no-neighbor nodes write the identity LUT (word0 = 0b10).
__global__ void k_pack_lut(const int* __restrict__ lut) {
    int wid  = (blockIdx.x * blockDim.x + threadIdx.x) >> 5;
    int lane = threadIdx.x & 31;
    if (wid >= N_NODES * LUTW) return;
    int node = wid >> 7, wofs = wid & 127;
    unsigned word;
    if (g_non[node]) {
        word = (wofs == 0) ? 2u : 0u;
    } else {
        int v = lut[(size_t)node * 4096 + (size_t)wofs * 32 + lane];
        word = __ballot_sync(0xffffffffu, v != 0);
    }
    if (lane == 0) g_lut[node * LUTW + wofs] = word;
}

__global__ void k_init(const int* __restrict__ init_states) {
    int i = blockIdx.x * blockDim.x + threadIdx.x;
    if (i == 0) { g_arrive = 0; g_gen = 0; }
    if (i >= ST_SZ) return;
    if (i < N_INPUT) {
        g_st[0][i] = g_u[i];                       // u[0][i]
    } else if (i < N_NODES) {
        int s = init_states[i];
        g_st[0][i] = s ? make_uint2(0xffffffffu, 0xffffffffu) : make_uint2(0u, 0u);
    } else {                                        // dummy + pad: zero both buffers
        g_st[0][i] = make_uint2(0u, 0u);
        g_st[1][i] = make_uint2(0u, 0u);
    }
}

// ---------------- main persistent kernel ----------------

// 32x32 bit-matrix transpose distributed across a warp (5 butterfly stages).
// In: lane l holds row l (bit j = col j). Out: lane j holds column j.
__device__ __forceinline__ unsigned btrans32(unsigned x, int lane) {
    unsigned y;
    y = __shfl_xor_sync(0xffffffffu, x, 16);
    x = (lane & 16) ? ((x & 0xffff0000u) | ((y & 0xffff0000u) >> 16))
                    : ((x & 0x0000ffffu) | ((y & 0x0000ffffu) << 16));
    y = __shfl_xor_sync(0xffffffffu, x, 8);
    x = (lane & 8)  ? ((x & 0xff00ff00u) | ((y & 0xff00ff00u) >> 8))
                    : ((x & 0x00ff00ffu) | ((y & 0x00ff00ffu) << 8));
    y = __shfl_xor_sync(0xffffffffu, x, 4);
    x = (lane & 4)  ? ((x & 0xf0f0f0f0u) | ((y & 0xf0f0f0f0u) >> 4))
                    : ((x & 0x0f0f0f0fu) | ((y & 0x0f0f0f0fu) << 4));
    y = __shfl_xor_sync(0xffffffffu, x, 2);
    x = (lane & 2)  ? ((x & 0xccccccccu) | ((y & 0xccccccccu) >> 2))
                    : ((x & 0x33333333u) | ((y & 0x33333333u) << 2));
    y = __shfl_xor_sync(0xffffffffu, x, 1);
    x = (lane & 1)  ? ((x & 0xaaaaaaaau) | ((y & 0xaaaaaaaau) >> 1))
                    : ((x & 0x55555555u) | ((y & 0x55555555u) << 1));
    return x;
}

// R1's validated barrier: atomic ticket + single-word broadcast spin.
__device__ __forceinline__ void grid_bar(int t, int nblocks) {
    __syncthreads();
    if (threadIdx.x == 0) {
        __threadfence();                                   // release this CTA's state writes
        unsigned tk = atomicAdd(&g_arrive, 1u);
        if (tk == (unsigned)(nblocks - 1)) {
            g_arrive = 0;
            __threadfence();
            g_gen = (unsigned)(t + 1);
        } else {
            while (g_gen <= (unsigned)t) { }               // volatile spin (L2)
        }
        __threadfence();
    }
    __syncthreads();
}

__global__ void __launch_bounds__(TPB_MAIN, 1) k_main() {
    const int lane = threadIdx.x & 31;
    const int gw   = blockIdx.x * (TPB_MAIN / 32) + (threadIdx.x >> 5);
    const int NW   = gridDim.x * (TPB_MAIN / 32);
    const int nb   = gridDim.x;
    int cur = 0;

    for (int t = 0; t < TSTEPS; t++) {
        const uint2* __restrict__ S = g_st[cur];
        uint2* __restrict__ D = g_st[cur ^ 1];

        // stage next step's input-layer bits into the destination buffer
        if (gw < 2 && t + 1 < TSTEPS) {
            int j = gw * 32 + lane;
            D[j] = g_u[(t + 1) * 64 + j];
        }

        for (int node = N_INPUT + gw; node < N_NODES; node += NW) {
            // only lanes 0..11 carry neighbor data; lanes 12..31 contribute 0 bits
            uint2 w = make_uint2(0u, 0u);
            if (lane < KMAX) {
                unsigned ai = (unsigned)g_adj[node * 16 + lane];   // L1-resident
                w = __ldcg(&S[ai]);           // L2-coherent (L1 stale across steps)
            }
            unsigned iL = btrans32(w.x, lane);   // lane j: 12-bit LUT idx for batch j
            unsigned iH = btrans32(w.y, lane);   // lane j: idx for batch 32+j
            const unsigned* __restrict__ row = g_lut + (unsigned)node * LUTW;
            unsigned bl = (__ldg(&row[iL >> 5]) >> (iL & 31)) & 1u;
            unsigned bh = (__ldg(&row[iH >> 5]) >> (iH & 31)) & 1u;
            unsigned nlo = __ballot_sync(0xffffffffu, bl);
            unsigned nhi = __ballot_sync(0xffffffffu, bh);
            if (lane == 0) D[node] = make_uint2(nlo, nhi);
        }

        grid_bar(t, nb);
        cur ^= 1;
    }
}

// ---------------- readout: sigmoid(states[:,64:] @ W^T + b) ----------------

__global__ void k_readout(const float* __restrict__ W, const float* __restrict__ bias,
                          float* __restrict__ out) {
    int b   = blockIdx.x;        // 64 blocks
    int tid = threadIdx.x;       // 256 threads
    int lane = tid & 31, wrp = tid >> 5;
    const uint2* __restrict__ S = g_st[0];   // TSTEPS even -> final states in buffer 0

    float acc[N_OUT];
#pragma unroll
    for (int o = 0; o < N_OUT; o++) acc[o] = 0.f;

    const int bsh = b & 31;
    for (int n = N_INPUT + tid; n < N_NODES; n += blockDim.x) {
        uint2 w = S[n];
        unsigned word = (b < 32) ? w.x : w.y;
        float bit = (float)((word >> bsh) & 1u);
        const float* wp = W + (n - N_INPUT);
#pragma unroll
        for (int o = 0; o < N_OUT; o++)
            acc[o] += bit * wp[o * (N_NODES - N_INPUT)];
    }

    __shared__ float part[8][N_OUT];
#pragma unroll
    for (int o = 0; o < N_OUT; o++) {
        float v = acc[o];
#pragma unroll
        for (int off = 16; off; off >>= 1) v += __shfl_down_sync(0xffffffffu, v, off);
        if (lane == 0) part[wrp][o] = v;
    }
    __syncthreads();
    if (tid < N_OUT) {
        float s = bias[tid];
#pragma unroll
        for (int w2 = 0; w2 < 8; w2++) s += part[w2][tid];
        out[b * N_OUT + tid] = 1.0f / (1.0f + expf(-s));
    }
}

// ---------------- launch ----------------

extern "C" void kernel_launch(void* const* d_in, const int* in_sizes, int n_in,
                              void* d_out, int out_size) {
    (void)in_sizes; (void)n_in; (void)out_size;
    const int*   x           = (const int*)d_in[0];
    const int*   w_in        = (const int*)d_in[1];
    const int*   adj_list    = (const int*)d_in[2];
    const int*   adj_mask    = (const int*)d_in[3];
    const int*   lut         = (const int*)d_in[4];
    const int*   init_states = (const int*)d_in[5];
    const float* W_out       = (const float*)d_in[6];
    const float* b_out       = (const float*)d_in[7];
    float* out = (float*)d_out;

    k_pack_x<<<(NBATCH * TSTEPS * 32) / 256, 256>>>(x);
    k_pack_w<<<8, 256>>>(w_in);
    k_build_u<<<(TSTEPS * 64 * 32) / 256, 256>>>();
    k_pack_adj<<<(N_NODES + 255) / 256, 256>>>(adj_list, adj_mask);
    k_pack_lut<<<(N_NODES * LUTW) / 8, 256>>>(lut);
    k_init<<<(ST_SZ + 255) / 256, 256>>>(init_states);

    int dev = 0, sms = GRID_MAIN;
    cudaGetDevice(&dev);
    cudaDeviceGetAttribute(&sms, cudaDevAttrMultiProcessorCount, dev);
    int grid = (sms < GRID_MAIN) ? sms : GRID_MAIN;   // wave-1 co-residency guaranteed

    k_main<<<grid, TPB_MAIN>>>();
    k_readout<<<NBATCH, 256>>>(W_out, b_out, out);
}

// round 5
// speedup vs baseline: 2.1958x; 1.3283x over previous
#include <cuda_runtime.h>
#include <cuda_bf16.h>
#include <cstdint>

#define N_NODES   20000
#define N_INPUT   64
#define KMAX      12
#define NBITS     64
#define N_OUT     10
#define NBATCH    64
#define TSTEPS    128
#define LUTW      128         /* 4096 bits / 32 words */
#define DUMMY     20000
#define ST_SZ     20008
#define TPB_MAIN  1024
#define NPC       136         /* nodes per CTA (even) */
#define PAIRS     (NPC / 2)   /* 68 */
#define GRID_MAIN 147         /* 147*136 = 19992 >= 19936 */
#define SLUT_WORDS (NPC * LUTW)          /* 17408 words */
#define SLUT_BYTES (SLUT_WORDS * 4)      /* 69632 bytes */

// ---------------- device globals (scratch; no allocations allowed) ----------------
__device__ __align__(16) unsigned short g_adj[N_NODES * 16];   // lane-reversed packed adjacency
__device__ unsigned int  g_lut[N_NODES * LUTW];                // 10.24 MB bit-packed LUT
__device__ unsigned char g_non[N_NODES];                       // no-neighbor flag per node
__device__ uint2         g_st[2][ST_SZ];                       // bit-packed states; slot 20000 = always-0 dummy
__device__ uint2         g_u[TSTEPS * 64];                     // input-layer bits u[t][j]
__device__ uint2         g_xb[NBATCH * TSTEPS];                // packed x bits [b][t]
__device__ uint2         g_wc[64];                             // packed w_in columns
__device__ unsigned int  g_arrive;
__device__ volatile unsigned int g_gen;

// ---------------- preprocessing ----------------

__global__ void k_pack_x(const int* __restrict__ x) {
    int wid  = (blockIdx.x * blockDim.x + threadIdx.x) >> 5;
    int lane = threadIdx.x & 31;
    if (wid >= NBATCH * TSTEPS) return;
    int b = wid >> 7, t = wid & 127;
    const int* p = x + ((size_t)b * TSTEPS + t) * NBITS;
    unsigned lo = __ballot_sync(0xffffffffu, p[lane] != 0);
    unsigned hi = __ballot_sync(0xffffffffu, p[lane + 32] != 0);
    if (lane == 0) g_xb[b * TSTEPS + t] = make_uint2(lo, hi);
}

__global__ void k_pack_w(const int* __restrict__ w_in) {
    int wid  = (blockIdx.x * blockDim.x + threadIdx.x) >> 5;
    int lane = threadIdx.x & 31;
    if (wid >= 64) return;
    unsigned lo = __ballot_sync(0xffffffffu, w_in[lane * 64 + wid] != 0);
    unsigned hi = __ballot_sync(0xffffffffu, w_in[(lane + 32) * 64 + wid] != 0);
    if (lane == 0) g_wc[wid] = make_uint2(lo, hi);
}

// u[t][j] bit b = ((x_bits[b][t] & w_col[j]) != 0)
__global__ void k_build_u() {
    int wid  = (blockIdx.x * blockDim.x + threadIdx.x) >> 5;
    int lane = threadIdx.x & 31;
    if (wid >= TSTEPS * 64) return;
    int t = wid >> 6, j = wid & 63;
    uint2 wc = g_wc[j];
    uint2 xa = g_xb[lane * TSTEPS + t];
    uint2 xb = g_xb[(lane + 32) * TSTEPS + t];
    unsigned lo = __ballot_sync(0xffffffffu, ((xa.x & wc.x) | (xa.y & wc.y)) != 0);
    unsigned hi = __ballot_sync(0xffffffffu, ((xb.x & wc.x) | (xb.y & wc.y)) != 0);
    if (lane == 0) g_u[t * 64 + j] = make_uint2(lo, hi);
}

// Fold adj_mask into adjacency, LANE-REVERSED (lane l = neighbor 11-l). Masked ->
// DUMMY (state always 0); no-neighbor nodes -> self at lane 0 with identity LUT.
__global__ void k_pack_adj(const int* __restrict__ adj_list, const int* __restrict__ adj_mask) {
    int n = blockIdx.x * blockDim.x + threadIdx.x;
    if (n >= N_NODES) return;
    unsigned a[12];
    int any = 0;
#pragma unroll
    for (int k = 0; k < KMAX; k++) {
        int m = adj_mask[n * KMAX + k];
        any |= m;
        a[k] = m ? (unsigned)adj_list[n * KMAX + k] : (unsigned)DUMMY;
    }
    if (!any) {
#pragma unroll
        for (int k = 0; k < KMAX; k++) a[k] = DUMMY;
        a[11] = (unsigned)n;   // idx = old state bit (identity LUT)
    }
    g_non[n] = (unsigned char)(!any);
    unsigned r[16];
#pragma unroll
    for (int l = 0; l < 12; l++) r[l] = a[11 - l];
    r[12] = r[13] = r[14] = r[15] = DUMMY;
    uint4 v0, v1;
    v0.x = r[0]  | (r[1]  << 16); v0.y = r[2]  | (r[3]  << 16);
    v0.z = r[4]  | (r[5]  << 16); v0.w = r[6]  | (r[7]  << 16);
    v1.x = r[8]  | (r[9]  << 16); v1.y = r[10] | (r[11] << 16);
    v1.z = r[12] | (r[13] << 16); v1.w = r[14] | (r[15] << 16);
    ((uint4*)g_adj)[n * 2]     = v0;
    ((uint4*)g_adj)[n * 2 + 1] = v1;
}

// Bit-pack the LUT. For no-neighbor nodes write the identity LUT (word0 = 0b10).
__global__ void k_pack_lut(const int* __restrict__ lut) {
    int wid  = (blockIdx.x * blockDim.x + threadIdx.x) >> 5;
    int lane = threadIdx.x & 31;
    if (wid >= N_NODES * LUTW) return;
    int node = wid >> 7, wofs = wid & 127;
    unsigned word;
    if (g_non[node]) {
        word = (wofs == 0) ? 2u : 0u;
    } else {
        int v = lut[(size_t)node * 4096 + (size_t)wofs * 32 + lane];
        word = __ballot_sync(0xffffffffu, v != 0);
    }
    if (lane == 0) g_lut[node * LUTW + wofs] = word;
}

__global__ void k_init(const int* __restrict__ init_states) {
    int i = blockIdx.x * blockDim.x + threadIdx.x;
    if (i == 0) { g_arrive = 0; g_gen = 0; }
    if (i >= ST_SZ) return;
    if (i < N_INPUT) {
        g_st[0][i] = g_u[i];                       // u[0][i]
    } else if (i < N_NODES) {
        int s = init_states[i];
        g_st[0][i] = s ? make_uint2(0xffffffffu, 0xffffffffu) : make_uint2(0u, 0u);
    } else {                                        // dummy + pad: zero both buffers
        g_st[0][i] = make_uint2(0u, 0u);
        g_st[1][i] = make_uint2(0u, 0u);
    }
}

// ---------------- main persistent kernel ----------------

// 32x32 bit-matrix transpose distributed across a warp (5 butterfly stages).
__device__ __forceinline__ unsigned btrans32(unsigned x, int lane) {
    unsigned y;
    y = __shfl_xor_sync(0xffffffffu, x, 16);
    x = (lane & 16) ? ((x & 0xffff0000u) | ((y & 0xffff0000u) >> 16))
                    : ((x & 0x0000ffffu) | ((y & 0x0000ffffu) << 16));
    y = __shfl_xor_sync(0xffffffffu, x, 8);
    x = (lane & 8)  ? ((x & 0xff00ff00u) | ((y & 0xff00ff00u) >> 8))
                    : ((x & 0x00ff00ffu) | ((y & 0x00ff00ffu) << 8));
    y = __shfl_xor_sync(0xffffffffu, x, 4);
    x = (lane & 4)  ? ((x & 0xf0f0f0f0u) | ((y & 0xf0f0f0f0u) >> 4))
                    : ((x & 0x0f0f0f0fu) | ((y & 0x0f0f0f0fu) << 4));
    y = __shfl_xor_sync(0xffffffffu, x, 2);
    x = (lane & 2)  ? ((x & 0xccccccccu) | ((y & 0xccccccccu) >> 2))
                    : ((x & 0x33333333u) | ((y & 0x33333333u) << 2));
    y = __shfl_xor_sync(0xffffffffu, x, 1);
    x = (lane & 1)  ? ((x & 0xaaaaaaaau) | ((y & 0xaaaaaaaau) >> 1))
                    : ((x & 0x55555555u) | ((y & 0x55555555u) << 1));
    return x;
}

// Twice-validated barrier: atomic ticket + single-word broadcast spin.
__device__ __forceinline__ void grid_bar(int t, int nblocks) {
    __syncthreads();
    if (threadIdx.x == 0) {
        __threadfence();                                   // release this CTA's state writes
        unsigned tk = atomicAdd(&g_arrive, 1u);
        if (tk == (unsigned)(nblocks - 1)) {
            g_arrive = 0;
            __threadfence();
            g_gen = (unsigned)(t + 1);
        } else {
            while (g_gen <= (unsigned)t) { }               // volatile spin (L2)
        }
        __threadfence();
    }
    __syncthreads();
}

__global__ void __launch_bounds__(TPB_MAIN, 1) k_main() {
    extern __shared__ unsigned s_lut[];                    // NPC * 128 words (68 KB)
    const int lane = threadIdx.x & 31;
    const int w    = threadIdx.x >> 5;                     // warp id in CTA (0..31)
    const int nb   = gridDim.x;
    const int start = N_INPUT + blockIdx.x * NPC;          // first node owned by this CTA

    // stage this CTA's LUT slice into shared memory (one-time)
    for (int i = threadIdx.x; i < SLUT_WORDS; i += TPB_MAIN) {
        int node = start + (i >> 7);
        s_lut[i] = (node < N_NODES) ? g_lut[node * LUTW + (i & 127)] : 0u;
    }

    // Pairing: pair p -> nodes (start+2p, start+2p+1). Warp w owns pairs
    // {w, w+32, w+64(<68)}. Lanes 0..11 hold A's lane-reversed adjacency,
    // lanes 16..27 hold B's; other lanes read the always-0 dummy.
    const bool laneA = (lane < KMAX);
    const bool laneB = (lane >= 16) && (lane < 16 + KMAX);
    const int  niters = (w < PAIRS - 64) ? 3 : 2;          // 68 = 32 + 32 + 4

    unsigned adjreg[3];
#pragma unroll
    for (int i = 0; i < 3; i++) {
        int p = w + i * 32;
        unsigned ai = DUMMY;
        if (p < PAIRS) {
            int nA = start + 2 * p, nB = nA + 1;
            if (laneA && nA < N_NODES) ai = (unsigned)g_adj[nA * 16 + lane];
            if (laneB && nB < N_NODES) ai = (unsigned)g_adj[nB * 16 + (lane - 16)];
        }
        adjreg[i] = ai;
    }
    __syncthreads();                                       // s_lut ready

    int cur = 0;
    for (int t = 0; t < TSTEPS; t++) {
        const uint2* __restrict__ S = g_st[cur];
        uint2* __restrict__ D = g_st[cur ^ 1];

        // CTA 0 stages next step's input-layer bits into the destination buffer
        if (blockIdx.x == 0 && threadIdx.x < 64 && t + 1 < TSTEPS)
            D[threadIdx.x] = g_u[(t + 1) * 64 + threadIdx.x];

#pragma unroll
        for (int i = 0; i < 3; i++) {
            if (i >= niters) break;
            int p  = w + i * 32;
            int nA = start + 2 * p;
            int nB = nA + 1;
            uint2 wv = make_uint2(0u, 0u);
            if (laneA || laneB) wv = __ldcg(&S[adjreg[i]]); // L2-coherent gather
            unsigned tl = btrans32(wv.x, lane);             // [idxA | idxB<<16] batches 0-31
            unsigned th = btrans32(wv.y, lane);             // batches 32-63
            unsigned iAL = tl & 0xfffu, iBL = (tl >> 16) & 0xfffu;
            unsigned iAH = th & 0xfffu, iBH = (th >> 16) & 0xfffu;
            const unsigned* rowA = s_lut + (p << 8);        // local node 2p
            const unsigned* rowB = rowA + LUTW;             // local node 2p+1
            unsigned bAL = (rowA[iAL >> 5] >> (iAL & 31)) & 1u;
            unsigned bAH = (rowA[iAH >> 5] >> (iAH & 31)) & 1u;
            unsigned bBL = (rowB[iBL >> 5] >> (iBL & 31)) & 1u;
            unsigned bBH = (rowB[iBH >> 5] >> (iBH & 31)) & 1u;
            unsigned mAL = __ballot_sync(0xffffffffu, bAL);
            unsigned mAH = __ballot_sync(0xffffffffu, bAH);
            unsigned mBL = __ballot_sync(0xffffffffu, bBL);
            unsigned mBH = __ballot_sync(0xffffffffu, bBH);
            if (lane == 0 && nA < N_NODES) D[nA] = make_uint2(mAL, mAH);
            if (lane == 1 && nB < N_NODES) D[nB] = make_uint2(mBL, mBH);
        }

        grid_bar(t, nb);
        cur ^= 1;
    }
}

// ---------------- readout: sigmoid(states[:,64:] @ W^T + b) ----------------

__global__ void k_readout(const float* __restrict__ W, const float* __restrict__ bias,
                          float* __restrict__ out) {
    int b   = blockIdx.x;        // 64 blocks
    int tid = threadIdx.x;       // 256 threads
    int lane = tid & 31, wrp = tid >> 5;
    const uint2* __restrict__ S = g_st[0];   // TSTEPS even -> final states in buffer 0

    float acc[N_OUT];
#pragma unroll
    for (int o = 0; o < N_OUT; o++) acc[o] = 0.f;

    const int bsh = b & 31;
    for (int n = N_INPUT + tid; n < N_NODES; n += blockDim.x) {
        uint2 w = S[n];
        unsigned word = (b < 32) ? w.x : w.y;
        float bit = (float)((word >> bsh) & 1u);
        const float* wp = W + (n - N_INPUT);
#pragma unroll
        for (int o = 0; o < N_OUT; o++)
            acc[o] += bit * wp[o * (N_NODES - N_INPUT)];
    }

    __shared__ float part[8][N_OUT];
#pragma unroll
    for (int o = 0; o < N_OUT; o++) {
        float v = acc[o];
#pragma unroll
        for (int off = 16; off; off >>= 1) v += __shfl_down_sync(0xffffffffu, v, off);
        if (lane == 0) part[wrp][o] = v;
    }
    __syncthreads();
    if (tid < N_OUT) {
        float s = bias[tid];
#pragma unroll
        for (int w2 = 0; w2 < 8; w2++) s += part[w2][tid];
        out[b * N_OUT + tid] = 1.0f / (1.0f + expf(-s));
    }
}

// ---------------- launch ----------------

extern "C" void kernel_launch(void* const* d_in, const int* in_sizes, int n_in,
                              void* d_out, int out_size) {
    (void)in_sizes; (void)n_in; (void)out_size;
    const int*   x           = (const int*)d_in[0];
    const int*   w_in        = (const int*)d_in[1];
    const int*   adj_list    = (const int*)d_in[2];
    const int*   adj_mask    = (const int*)d_in[3];
    const int*   lut         = (const int*)d_in[4];
    const int*   init_states = (const int*)d_in[5];
    const float* W_out       = (const float*)d_in[6];
    const float* b_out       = (const float*)d_in[7];
    float* out = (float*)d_out;

    k_pack_x<<<(NBATCH * TSTEPS * 32) / 256, 256>>>(x);
    k_pack_w<<<8, 256>>>(w_in);
    k_build_u<<<(TSTEPS * 64 * 32) / 256, 256>>>();
    k_pack_adj<<<(N_NODES + 255) / 256, 256>>>(adj_list, adj_mask);
    k_pack_lut<<<(N_NODES * LUTW) / 8, 256>>>(lut);
    k_init<<<(ST_SZ + 255) / 256, 256>>>(init_states);

    cudaFuncSetAttribute(k_main, cudaFuncAttributeMaxDynamicSharedMemorySize, SLUT_BYTES);
    k_main<<<GRID_MAIN, TPB_MAIN, SLUT_BYTES>>>();
    k_readout<<<NBATCH, 256>>>(W_out, b_out, out);
}

// round 6
// speedup vs baseline: 2.3520x; 1.0711x over previous
#include <cuda_runtime.h>
#include <cuda_bf16.h>
#include <cstdint>

#define N_NODES   20000
#define N_INPUT   64
#define KMAX      12
#define NBITS     64
#define N_OUT     10
#define NBATCH    64
#define TSTEPS    128
#define LUTW      128         /* 4096 bits / 32 words */
#define DUMMY     20000
#define ST_SZ     20008
#define TPB_MAIN  1024
#define NPC       136         /* nodes per CTA (even) */
#define PAIRS     (NPC / 2)   /* 68 */
#define GRID_MAIN 147         /* 147*136 = 19992 >= 19936 */
#define SLUT_WORDS (NPC * LUTW)          /* 17408 words */
#define SLUT_BYTES (SLUT_WORDS * 4)      /* 69632 bytes */

// ---------------- device globals (scratch; no allocations allowed) ----------------
__device__ __align__(16) unsigned short g_adj[N_NODES * 16];   // lane-reversed packed adjacency
__device__ unsigned int  g_lut[N_NODES * LUTW];                // 10.24 MB bit-packed LUT
__device__ unsigned char g_non[N_NODES];                       // no-neighbor flag per node
__device__ uint2         g_st[2][ST_SZ];                       // bit-packed states; slot 20000 = always-0 dummy
__device__ uint2         g_u[TSTEPS * 64];                     // input-layer bits u[t][j]
__device__ uint2         g_xb[NBATCH * TSTEPS];                // packed x bits [b][t]
__device__ uint2         g_wc[64];                             // packed w_in columns
__device__ unsigned int  g_arrive;                             // MONOTONIC arrival counter

// ---------------- preprocessing ----------------

__global__ void k_pack_x(const int* __restrict__ x) {
    int wid  = (blockIdx.x * blockDim.x + threadIdx.x) >> 5;
    int lane = threadIdx.x & 31;
    if (wid >= NBATCH * TSTEPS) return;
    int b = wid >> 7, t = wid & 127;
    const int* p = x + ((size_t)b * TSTEPS + t) * NBITS;
    unsigned lo = __ballot_sync(0xffffffffu, p[lane] != 0);
    unsigned hi = __ballot_sync(0xffffffffu, p[lane + 32] != 0);
    if (lane == 0) g_xb[b * TSTEPS + t] = make_uint2(lo, hi);
}

__global__ void k_pack_w(const int* __restrict__ w_in) {
    int wid  = (blockIdx.x * blockDim.x + threadIdx.x) >> 5;
    int lane = threadIdx.x & 31;
    if (wid >= 64) return;
    unsigned lo = __ballot_sync(0xffffffffu, w_in[lane * 64 + wid] != 0);
    unsigned hi = __ballot_sync(0xffffffffu, w_in[(lane + 32) * 64 + wid] != 0);
    if (lane == 0) g_wc[wid] = make_uint2(lo, hi);
}

// u[t][j] bit b = ((x_bits[b][t] & w_col[j]) != 0)
__global__ void k_build_u() {
    int wid  = (blockIdx.x * blockDim.x + threadIdx.x) >> 5;
    int lane = threadIdx.x & 31;
    if (wid >= TSTEPS * 64) return;
    int t = wid >> 6, j = wid & 63;
    uint2 wc = g_wc[j];
    uint2 xa = g_xb[lane * TSTEPS + t];
    uint2 xb = g_xb[(lane + 32) * TSTEPS + t];
    unsigned lo = __ballot_sync(0xffffffffu, ((xa.x & wc.x) | (xa.y & wc.y)) != 0);
    unsigned hi = __ballot_sync(0xffffffffu, ((xb.x & wc.x) | (xb.y & wc.y)) != 0);
    if (lane == 0) g_u[t * 64 + j] = make_uint2(lo, hi);
}

// Fold adj_mask into adjacency, LANE-REVERSED (lane l = neighbor 11-l). Masked ->
// DUMMY (state always 0); no-neighbor nodes -> self at lane 0 with identity LUT.
__global__ void k_pack_adj(const int* __restrict__ adj_list, const int* __restrict__ adj_mask) {
    int n = blockIdx.x * blockDim.x + threadIdx.x;
    if (n >= N_NODES) return;
    unsigned a[12];
    int any = 0;
#pragma unroll
    for (int k = 0; k < KMAX; k++) {
        int m = adj_mask[n * KMAX + k];
        any |= m;
        a[k] = m ? (unsigned)adj_list[n * KMAX + k] : (unsigned)DUMMY;
    }
    if (!any) {
#pragma unroll
        for (int k = 0; k < KMAX; k++) a[k] = DUMMY;
        a[11] = (unsigned)n;   // idx = old state bit (identity LUT)
    }
    g_non[n] = (unsigned char)(!any);
    unsigned r[16];
#pragma unroll
    for (int l = 0; l < 12; l++) r[l] = a[11 - l];
    r[12] = r[13] = r[14] = r[15] = DUMMY;
    uint4 v0, v1;
    v0.x = r[0]  | (r[1]  << 16); v0.y = r[2]  | (r[3]  << 16);
    v0.z = r[4]  | (r[5]  << 16); v0.w = r[6]  | (r[7]  << 16);
    v1.x = r[8]  | (r[9]  << 16); v1.y = r[10] | (r[11] << 16);
    v1.z = r[12] | (r[13] << 16); v1.w = r[14] | (r[15] << 16);
    ((uint4*)g_adj)[n * 2]     = v0;
    ((uint4*)g_adj)[n * 2 + 1] = v1;
}

// Bit-pack the LUT. For no-neighbor nodes write the identity LUT (word0 = 0b10).
__global__ void k_pack_lut(const int* __restrict__ lut) {
    int wid  = (blockIdx.x * blockDim.x + threadIdx.x) >> 5;
    int lane = threadIdx.x & 31;
    if (wid >= N_NODES * LUTW) return;
    int node = wid >> 7, wofs = wid & 127;
    unsigned word;
    if (g_non[node]) {
        word = (wofs == 0) ? 2u : 0u;
    } else {
        int v = lut[(size_t)node * 4096 + (size_t)wofs * 32 + lane];
        word = __ballot_sync(0xffffffffu, v != 0);
    }
    if (lane == 0) g_lut[node * LUTW + wofs] = word;
}

__global__ void k_init(const int* __restrict__ init_states) {
    int i = blockIdx.x * blockDim.x + threadIdx.x;
    if (i == 0) g_arrive = 0;
    if (i >= ST_SZ) return;
    if (i < N_INPUT) {
        g_st[0][i] = g_u[i];                       // u[0][i]
    } else if (i < N_NODES) {
        int s = init_states[i];
        g_st[0][i] = s ? make_uint2(0xffffffffu, 0xffffffffu) : make_uint2(0u, 0u);
    } else {                                        // dummy + pad: zero both buffers
        g_st[0][i] = make_uint2(0u, 0u);
        g_st[1][i] = make_uint2(0u, 0u);
    }
}

// ---------------- main persistent kernel ----------------

// 32x32 bit-matrix transpose distributed across a warp (5 butterfly stages).
__device__ __forceinline__ unsigned btrans32(unsigned x, int lane) {
    unsigned y;
    y = __shfl_xor_sync(0xffffffffu, x, 16);
    x = (lane & 16) ? ((x & 0xffff0000u) | ((y & 0xffff0000u) >> 16))
                    : ((x & 0x0000ffffu) | ((y & 0x0000ffffu) << 16));
    y = __shfl_xor_sync(0xffffffffu, x, 8);
    x = (lane & 8)  ? ((x & 0xff00ff00u) | ((y & 0xff00ff00u) >> 8))
                    : ((x & 0x00ff00ffu) | ((y & 0x00ff00ffu) << 8));
    y = __shfl_xor_sync(0xffffffffu, x, 4);
    x = (lane & 4)  ? ((x & 0xf0f0f0f0u) | ((y & 0xf0f0f0f0u) >> 4))
                    : ((x & 0x0f0f0f0fu) | ((y & 0x0f0f0f0fu) << 4));
    y = __shfl_xor_sync(0xffffffffu, x, 2);
    x = (lane & 2)  ? ((x & 0xccccccccu) | ((y & 0xccccccccu) >> 2))
                    : ((x & 0x33333333u) | ((y & 0x33333333u) << 2));
    y = __shfl_xor_sync(0xffffffffu, x, 1);
    x = (lane & 1)  ? ((x & 0xaaaaaaaau) | ((y & 0xaaaaaaaau) >> 1))
                    : ((x & 0x55555555u) | ((y & 0x55555555u) << 1));
    return x;
}

// Monotonic REDG barrier: arrive = atomicAdd with DISCARDED return (ptxas emits
// RED, 0.854 cyc/op at one address vs ~27 cyc for contended ATOMG-with-return);
// wait = single-hop spin until counter reaches nblocks*(t+1). Never reset.
__device__ __forceinline__ void grid_bar(int t, int nblocks) {
    __syncthreads();
    if (threadIdx.x == 0) {
        __threadfence();                                   // release this CTA's state writes
        atomicAdd(&g_arrive, 1u);                          // return unused -> REDG
        const unsigned target = (unsigned)nblocks * (unsigned)(t + 1);
        while (*(volatile unsigned*)&g_arrive < target) { }
        __threadfence();                                   // acquire
    }
    __syncthreads();
}

__global__ void __launch_bounds__(TPB_MAIN, 1) k_main() {
    extern __shared__ unsigned s_lut[];                    // NPC * 128 words (68 KB)
    const int lane = threadIdx.x & 31;
    const int w    = threadIdx.x >> 5;                     // warp id in CTA (0..31)
    const int nb   = gridDim.x;
    const int start = N_INPUT + blockIdx.x * NPC;          // first node owned by this CTA

    // stage this CTA's LUT slice into shared memory (one-time)
    for (int i = threadIdx.x; i < SLUT_WORDS; i += TPB_MAIN) {
        int node = start + (i >> 7);
        s_lut[i] = (node < N_NODES) ? g_lut[node * LUTW + (i & 127)] : 0u;
    }

    // Pairing: pair p -> nodes (start+2p, start+2p+1). Warp w owns pairs
    // {w, w+32, w+64(<68)}. Lanes 0..11 hold A's lane-reversed adjacency,
    // lanes 16..27 hold B's; other lanes read the always-0 dummy.
    const bool laneA = (lane < KMAX);
    const bool laneB = (lane >= 16) && (lane < 16 + KMAX);
    const bool gath  = laneA || laneB;
    const int  niters = (w < PAIRS - 64) ? 3 : 2;          // 68 = 32 + 32 + 4

    unsigned adjreg[3];
#pragma unroll
    for (int i = 0; i < 3; i++) {
        int p = w + i * 32;
        unsigned ai = DUMMY;
        if (p < PAIRS) {
            int nA = start + 2 * p, nB = nA + 1;
            if (laneA && nA < N_NODES) ai = (unsigned)g_adj[nA * 16 + lane];
            if (laneB && nB < N_NODES) ai = (unsigned)g_adj[nB * 16 + (lane - 16)];
        }
        adjreg[i] = ai;
    }
    __syncthreads();                                       // s_lut ready

    int cur = 0;
    for (int t = 0; t < TSTEPS; t++) {
        const uint2* __restrict__ S = g_st[cur];
        uint2* __restrict__ D = g_st[cur ^ 1];

        // CTA 0 stages next step's input-layer bits into the destination buffer
        if (blockIdx.x == 0 && threadIdx.x < 64 && t + 1 < TSTEPS)
            D[threadIdx.x] = g_u[(t + 1) * 64 + threadIdx.x];

#pragma unroll
        for (int i = 0; i < 3; i++) {
            if (i >= niters) break;
            int p  = w + i * 32;
            int nA = start + 2 * p;
            int nB = nA + 1;
            uint2 wv = make_uint2(0u, 0u);
            if (gath) wv = __ldcg(&S[adjreg[i]]);           // L2-coherent gather
            unsigned tl = btrans32(wv.x, lane);             // [idxA | idxB<<16] batches 0-31
            unsigned th = btrans32(wv.y, lane);             // batches 32-63
            unsigned iAL = tl & 0xfffu, iBL = (tl >> 16) & 0xfffu;
            unsigned iAH = th & 0xfffu, iBH = (th >> 16) & 0xfffu;
            const unsigned* rowA = s_lut + (p << 8);        // local node 2p
            const unsigned* rowB = rowA + LUTW;             // local node 2p+1
            unsigned bAL = (rowA[iAL >> 5] >> (iAL & 31)) & 1u;
            unsigned bAH = (rowA[iAH >> 5] >> (iAH & 31)) & 1u;
            unsigned bBL = (rowB[iBL >> 5] >> (iBL & 31)) & 1u;
            unsigned bBH = (rowB[iBH >> 5] >> (iBH & 31)) & 1u;
            unsigned mAL = __ballot_sync(0xffffffffu, bAL);
            unsigned mAH = __ballot_sync(0xffffffffu, bAH);
            unsigned mBL = __ballot_sync(0xffffffffu, bBL);
            unsigned mBH = __ballot_sync(0xffffffffu, bBH);
            if (lane == 0 && nA < N_NODES) D[nA] = make_uint2(mAL, mAH);
            if (lane == 1 && nB < N_NODES) D[nB] = make_uint2(mBL, mBH);
        }

        grid_bar(t, nb);
        cur ^= 1;
    }
}

// ---------------- readout: sigmoid(states[:,64:] @ W^T + b) ----------------

__global__ void k_readout(const float* __restrict__ W, const float* __restrict__ bias,
                          float* __restrict__ out) {
    int b   = blockIdx.x;        // 64 blocks
    int tid = threadIdx.x;       // 256 threads
    int lane = tid & 31, wrp = tid >> 5;
    const uint2* __restrict__ S = g_st[0];   // TSTEPS even -> final states in buffer 0

    float acc[N_OUT];
#pragma unroll
    for (int o = 0; o < N_OUT; o++) acc[o] = 0.f;

    const int bsh = b & 31;
    for (int n = N_INPUT + tid; n < N_NODES; n += blockDim.x) {
        uint2 w = S[n];
        unsigned word = (b < 32) ? w.x : w.y;
        float bit = (float)((word >> bsh) & 1u);
        const float* wp = W + (n - N_INPUT);
#pragma unroll
        for (int o = 0; o < N_OUT; o++)
            acc[o] += bit * wp[o * (N_NODES - N_INPUT)];
    }

    __shared__ float part[8][N_OUT];
#pragma unroll
    for (int o = 0; o < N_OUT; o++) {
        float v = acc[o];
#pragma unroll
        for (int off = 16; off; off >>= 1) v += __shfl_down_sync(0xffffffffu, v, off);
        if (lane == 0) part[wrp][o] = v;
    }
    __syncthreads();
    if (tid < N_OUT) {
        float s = bias[tid];
#pragma unroll
        for (int w2 = 0; w2 < 8; w2++) s += part[w2][tid];
        out[b * N_OUT + tid] = 1.0f / (1.0f + expf(-s));
    }
}

// ---------------- launch ----------------

extern "C" void kernel_launch(void* const* d_in, const int* in_sizes, int n_in,
                              void* d_out, int out_size) {
    (void)in_sizes; (void)n_in; (void)out_size;
    const int*   x           = (const int*)d_in[0];
    const int*   w_in        = (const int*)d_in[1];
    const int*   adj_list    = (const int*)d_in[2];
    const int*   adj_mask    = (const int*)d_in[3];
    const int*   lut         = (const int*)d_in[4];
    const int*   init_states = (const int*)d_in[5];
    const float* W_out       = (const float*)d_in[6];
    const float* b_out       = (const float*)d_in[7];
    float* out = (float*)d_out;

    k_pack_x<<<(NBATCH * TSTEPS * 32) / 256, 256>>>(x);
    k_pack_w<<<8, 256>>>(w_in);
    k_build_u<<<(TSTEPS * 64 * 32) / 256, 256>>>();
    k_pack_adj<<<(N_NODES + 255) / 256, 256>>>(adj_list, adj_mask);
    k_pack_lut<<<(N_NODES * LUTW) / 8, 256>>>(lut);
    k_init<<<(ST_SZ + 255) / 256, 256>>>(init_states);

    cudaFuncSetAttribute(k_main, cudaFuncAttributeMaxDynamicSharedMemorySize, SLUT_BYTES);
    k_main<<<GRID_MAIN, TPB_MAIN, SLUT_BYTES>>>();
    k_readout<<<NBATCH, 256>>>(W_out, b_out, out);
}

// round 7
// speedup vs baseline: 2.6891x; 1.1433x over previous
#include <cuda_runtime.h>
#include <cuda_bf16.h>
#include <cstdint>

#define N_NODES   20000
#define N_INPUT   64
#define KMAX      12
#define NBITS     64
#define N_OUT     10
#define NBATCH    64
#define TSTEPS    128
#define LUTW      128         /* 4096 bits / 32 words */
#define DUMMY     20000
#define ST_SZ     20008
#define TPB_MAIN  1024
#define NPC       136         /* nodes per CTA (even) */
#define PAIRS     (NPC / 2)   /* 68 */
#define GRID_MAIN 147         /* 147*136 = 19992 >= 19936 */
#define SLUT_WORDS (NPC * LUTW)          /* 17408 words */
#define SLUT_BYTES (SLUT_WORDS * 4)      /* 69632 bytes */

// LUT bit layout (remapped for vectorized packing):
//   entry e -> word ((e>>7)<<2) | (e&3),  bit (e>>2)&31

// ---------------- device globals (scratch; no allocations allowed) ----------------
__device__ __align__(16) unsigned short g_adj[N_NODES * 16];   // lane-reversed packed adjacency
__device__ __align__(16) unsigned int g_lut[N_NODES * LUTW];   // 10.24 MB bit-packed LUT (remapped layout)
__device__ unsigned char g_non[N_NODES];                       // no-neighbor flag per node
__device__ uint2         g_st[2][ST_SZ];                       // bit-packed states; slot 20000 = always-0 dummy
__device__ uint2         g_u[TSTEPS * 64];                     // input-layer bits u[t][j]
__device__ uint2         g_xb[NBATCH * TSTEPS];                // packed x bits [b][t]
__device__ uint2         g_wc[64];                             // packed w_in columns
__device__ unsigned int  g_arrive;                             // MONOTONIC arrival counter

// ---------------- preprocessing (fused: 3 kernels) ----------------

// pre1: pack_x (blocks 0..1023) + pack_w (blocks 1024..1031)
__global__ void k_pre1(const int* __restrict__ x, const int* __restrict__ w_in) {
    int lane = threadIdx.x & 31;
    if (blockIdx.x < 1024) {
        int wid = (blockIdx.x * 256 + threadIdx.x) >> 5;   // 0..8191
        int b = wid >> 7, t = wid & 127;
        const int* p = x + ((size_t)b * TSTEPS + t) * NBITS;
        unsigned lo = __ballot_sync(0xffffffffu, p[lane] != 0);
        unsigned hi = __ballot_sync(0xffffffffu, p[lane + 32] != 0);
        if (lane == 0) g_xb[b * TSTEPS + t] = make_uint2(lo, hi);
    } else {
        int wid = ((blockIdx.x - 1024) * 256 + threadIdx.x) >> 5;  // 0..63
        unsigned lo = __ballot_sync(0xffffffffu, w_in[lane * 64 + wid] != 0);
        unsigned hi = __ballot_sync(0xffffffffu, w_in[(lane + 32) * 64 + wid] != 0);
        if (lane == 0) g_wc[wid] = make_uint2(lo, hi);
    }
}

// pre2: build_u (blocks 0..1023) + pack_adj (blocks 1024..1102)
__global__ void k_pre2(const int* __restrict__ adj_list, const int* __restrict__ adj_mask) {
    int lane = threadIdx.x & 31;
    if (blockIdx.x < 1024) {
        int wid = (blockIdx.x * 256 + threadIdx.x) >> 5;   // 0..8191
        int t = wid >> 6, j = wid & 63;
        uint2 wc = g_wc[j];
        uint2 xa = g_xb[lane * TSTEPS + t];
        uint2 xb = g_xb[(lane + 32) * TSTEPS + t];
        unsigned lo = __ballot_sync(0xffffffffu, ((xa.x & wc.x) | (xa.y & wc.y)) != 0);
        unsigned hi = __ballot_sync(0xffffffffu, ((xb.x & wc.x) | (xb.y & wc.y)) != 0);
        if (lane == 0) g_u[t * 64 + j] = make_uint2(lo, hi);
    } else {
        int n = (blockIdx.x - 1024) * 256 + threadIdx.x;
        if (n >= N_NODES) return;
        unsigned a[12];
        int any = 0;
#pragma unroll
        for (int k = 0; k < KMAX; k++) {
            int m = adj_mask[n * KMAX + k];
            any |= m;
            a[k] = m ? (unsigned)adj_list[n * KMAX + k] : (unsigned)DUMMY;
        }
        if (!any) {
#pragma unroll
            for (int k = 0; k < KMAX; k++) a[k] = DUMMY;
            a[11] = (unsigned)n;   // idx = old state bit (identity LUT)
        }
        g_non[n] = (unsigned char)(!any);
        unsigned r[16];
#pragma unroll
        for (int l = 0; l < 12; l++) r[l] = a[11 - l];     // lane-reversed
        r[12] = r[13] = r[14] = r[15] = DUMMY;
        uint4 v0, v1;
        v0.x = r[0]  | (r[1]  << 16); v0.y = r[2]  | (r[3]  << 16);
        v0.z = r[4]  | (r[5]  << 16); v0.w = r[6]  | (r[7]  << 16);
        v1.x = r[8]  | (r[9]  << 16); v1.y = r[10] | (r[11] << 16);
        v1.z = r[12] | (r[13] << 16); v1.w = r[14] | (r[15] << 16);
        ((uint4*)g_adj)[n * 2]     = v0;
        ((uint4*)g_adj)[n * 2 + 1] = v1;
    }
}

// pre3: pack_lut vectorized (blocks 0..79999) + state init (blocks 80000..80078).
// One warp per (node, 128-entry chunk): int4 load (16B/lane), 4 ballots -> 4 words,
// lane 0 stores uint4. Identity LUT for no-neighbor nodes: entry1 -> word1 bit0.
__global__ void k_pre3(const int* __restrict__ lut, const int* __restrict__ init_states) {
    if (blockIdx.x < 80000) {
        int gw   = blockIdx.x * 8 + (threadIdx.x >> 5);    // 0..639999
        int lane = threadIdx.x & 31;
        int node = gw >> 5, chunk = gw & 31;
        uint4 wout;
        if (g_non[node]) {
            wout = make_uint4(0u, (chunk == 0) ? 1u : 0u, 0u, 0u);
        } else {
            const int4* p = (const int4*)(lut + (size_t)node * 4096 + (size_t)chunk * 128);
            int4 v = p[lane];
            wout.x = __ballot_sync(0xffffffffu, v.x != 0);
            wout.y = __ballot_sync(0xffffffffu, v.y != 0);
            wout.z = __ballot_sync(0xffffffffu, v.z != 0);
            wout.w = __ballot_sync(0xffffffffu, v.w != 0);
        }
        if (lane == 0)
            ((uint4*)g_lut)[node * (LUTW / 4) + chunk] = wout;
    } else {
        int i = (blockIdx.x - 80000) * 256 + threadIdx.x;
        if (i == 0) g_arrive = 0;
        if (i >= ST_SZ) return;
        if (i < N_INPUT) {
            g_st[0][i] = g_u[i];                           // u[0][i]
        } else if (i < N_NODES) {
            int s = init_states[i];
            g_st[0][i] = s ? make_uint2(0xffffffffu, 0xffffffffu) : make_uint2(0u, 0u);
        } else {                                            // dummy + pad: zero both buffers
            g_st[0][i] = make_uint2(0u, 0u);
            g_st[1][i] = make_uint2(0u, 0u);
        }
    }
}

// ---------------- main persistent kernel ----------------

// 32x32 bit-matrix transpose distributed across a warp (5 butterfly stages).
__device__ __forceinline__ unsigned btrans32(unsigned x, int lane) {
    unsigned y;
    y = __shfl_xor_sync(0xffffffffu, x, 16);
    x = (lane & 16) ? ((x & 0xffff0000u) | ((y & 0xffff0000u) >> 16))
                    : ((x & 0x0000ffffu) | ((y & 0x0000ffffu) << 16));
    y = __shfl_xor_sync(0xffffffffu, x, 8);
    x = (lane & 8)  ? ((x & 0xff00ff00u) | ((y & 0xff00ff00u) >> 8))
                    : ((x & 0x00ff00ffu) | ((y & 0x00ff00ffu) << 8));
    y = __shfl_xor_sync(0xffffffffu, x, 4);
    x = (lane & 4)  ? ((x & 0xf0f0f0f0u) | ((y & 0xf0f0f0f0u) >> 4))
                    : ((x & 0x0f0f0f0fu) | ((y & 0x0f0f0f0fu) << 4));
    y = __shfl_xor_sync(0xffffffffu, x, 2);
    x = (lane & 2)  ? ((x & 0xccccccccu) | ((y & 0xccccccccu) >> 2))
                    : ((x & 0x33333333u) | ((y & 0x33333333u) << 2));
    y = __shfl_xor_sync(0xffffffffu, x, 1);
    x = (lane & 1)  ? ((x & 0xaaaaaaaau) | ((y & 0xaaaaaaaau) >> 1))
                    : ((x & 0x55555555u) | ((y & 0x55555555u) << 1));
    return x;
}

// remapped-layout LUT lookup: entry idx -> word ((idx>>7)<<2)|(idx&3), bit (idx>>2)&31
__device__ __forceinline__ unsigned lut_bit(const unsigned* __restrict__ row, unsigned idx) {
    unsigned wofs = ((idx >> 5) & ~3u) | (idx & 3u);
    return (row[wofs] >> ((idx >> 2) & 31u)) & 1u;
}

// Monotonic REDG barrier (validated): no-return atomicAdd + single-hop spin.
__device__ __forceinline__ void grid_bar(int t, int nblocks) {
    __syncthreads();
    if (threadIdx.x == 0) {
        __threadfence();                                   // release this CTA's state writes
        atomicAdd(&g_arrive, 1u);                          // return unused -> REDG
        const unsigned target = (unsigned)nblocks * (unsigned)(t + 1);
        while (*(volatile unsigned*)&g_arrive < target) { }
        __threadfence();                                   // acquire
    }
    __syncthreads();
}

__global__ void __launch_bounds__(TPB_MAIN, 1) k_main() {
    extern __shared__ unsigned s_lut[];                    // NPC * 128 words (68 KB)
    const int lane = threadIdx.x & 31;
    const int w    = threadIdx.x >> 5;                     // warp id in CTA (0..31)
    const int nb   = gridDim.x;
    const int start = N_INPUT + blockIdx.x * NPC;          // first node owned by this CTA

    // stage this CTA's LUT slice into shared memory (one-time)
    for (int i = threadIdx.x; i < SLUT_WORDS; i += TPB_MAIN) {
        int node = start + (i >> 7);
        s_lut[i] = (node < N_NODES) ? g_lut[node * LUTW + (i & 127)] : 0u;
    }

    // Pairing: pair p -> nodes (start+2p, start+2p+1). Warp w owns pairs
    // {w, w+32, w+64(<68)}. Lanes 0..11 hold A's lane-reversed adjacency,
    // lanes 16..27 hold B's; other lanes read the always-0 dummy.
    const bool laneA = (lane < KMAX);
    const bool laneB = (lane >= 16) && (lane < 16 + KMAX);
    const bool gath  = laneA || laneB;
    const int  niters = (w < PAIRS - 64) ? 3 : 2;          // 68 = 32 + 32 + 4

    unsigned adjreg[3];
#pragma unroll
    for (int i = 0; i < 3; i++) {
        int p = w + i * 32;
        unsigned ai = DUMMY;
        if (p < PAIRS) {
            int nA = start + 2 * p, nB = nA + 1;
            if (laneA && nA < N_NODES) ai = (unsigned)g_adj[nA * 16 + lane];
            if (laneB && nB < N_NODES) ai = (unsigned)g_adj[nB * 16 + (lane - 16)];
        }
        adjreg[i] = ai;
    }
    __syncthreads();                                       // s_lut ready

    int cur = 0;
    for (int t = 0; t < TSTEPS; t++) {
        const uint2* __restrict__ S = g_st[cur];
        uint2* __restrict__ D = g_st[cur ^ 1];

        // CTA 0 stages next step's input-layer bits into the destination buffer
        if (blockIdx.x == 0 && threadIdx.x < 64 && t + 1 < TSTEPS)
            D[threadIdx.x] = g_u[(t + 1) * 64 + threadIdx.x];

        // prefetch ALL of this warp's gathers before any compute (hide L2 latency)
        uint2 wv[3];
        wv[0] = wv[1] = wv[2] = make_uint2(0u, 0u);
        if (gath) {
            wv[0] = __ldcg(&S[adjreg[0]]);
            wv[1] = __ldcg(&S[adjreg[1]]);
            if (niters == 3) wv[2] = __ldcg(&S[adjreg[2]]);
        }

#pragma unroll
        for (int i = 0; i < 3; i++) {
            if (i >= niters) break;
            int p  = w + i * 32;
            int nA = start + 2 * p;
            int nB = nA + 1;
            unsigned tl = btrans32(wv[i].x, lane);          // [idxA | idxB<<16] batches 0-31
            unsigned th = btrans32(wv[i].y, lane);          // batches 32-63
            unsigned iAL = tl & 0xfffu, iBL = (tl >> 16) & 0xfffu;
            unsigned iAH = th & 0xfffu, iBH = (th >> 16) & 0xfffu;
            const unsigned* rowA = s_lut + (p << 8);        // local node 2p
            const unsigned* rowB = rowA + LUTW;             // local node 2p+1
            unsigned bAL = lut_bit(rowA, iAL);
            unsigned bAH = lut_bit(rowA, iAH);
            unsigned bBL = lut_bit(rowB, iBL);
            unsigned bBH = lut_bit(rowB, iBH);
            unsigned mAL = __ballot_sync(0xffffffffu, bAL);
            unsigned mAH = __ballot_sync(0xffffffffu, bAH);
            unsigned mBL = __ballot_sync(0xffffffffu, bBL);
            unsigned mBH = __ballot_sync(0xffffffffu, bBH);
            if (lane == 0 && nA < N_NODES) D[nA] = make_uint2(mAL, mAH);
            if (lane == 1 && nB < N_NODES) D[nB] = make_uint2(mBL, mBH);
        }

        grid_bar(t, nb);
        cur ^= 1;
    }
}

// ---------------- readout: sigmoid(states[:,64:] @ W^T + b) ----------------

__global__ void k_readout(const float* __restrict__ W, const float* __restrict__ bias,
                          float* __restrict__ out) {
    int b   = blockIdx.x;        // 64 blocks
    int tid = threadIdx.x;       // 256 threads
    int lane = tid & 31, wrp = tid >> 5;
    const uint2* __restrict__ S = g_st[0];   // TSTEPS even -> final states in buffer 0

    float acc[N_OUT];
#pragma unroll
    for (int o = 0; o < N_OUT; o++) acc[o] = 0.f;

    const int bsh = b & 31;
    for (int n = N_INPUT + tid; n < N_NODES; n += blockDim.x) {
        uint2 w = S[n];
        unsigned word = (b < 32) ? w.x : w.y;
        float bit = (float)((word >> bsh) & 1u);
        const float* wp = W + (n - N_INPUT);
#pragma unroll
        for (int o = 0; o < N_OUT; o++)
            acc[o] += bit * wp[o * (N_NODES - N_INPUT)];
    }

    __shared__ float part[8][N_OUT];
#pragma unroll
    for (int o = 0; o < N_OUT; o++) {
        float v = acc[o];
#pragma unroll
        for (int off = 16; off; off >>= 1) v += __shfl_down_sync(0xffffffffu, v, off);
        if (lane == 0) part[wrp][o] = v;
    }
    __syncthreads();
    if (tid < N_OUT) {
        float s = bias[tid];
#pragma unroll
        for (int w2 = 0; w2 < 8; w2++) s += part[w2][tid];
        out[b * N_OUT + tid] = 1.0f / (1.0f + expf(-s));
    }
}

// ---------------- launch ----------------

extern "C" void kernel_launch(void* const* d_in, const int* in_sizes, int n_in,
                              void* d_out, int out_size) {
    (void)in_sizes; (void)n_in; (void)out_size;
    const int*   x           = (const int*)d_in[0];
    const int*   w_in        = (const int*)d_in[1];
    const int*   adj_list    = (const int*)d_in[2];
    const int*   adj_mask    = (const int*)d_in[3];
    const int*   lut         = (const int*)d_in[4];
    const int*   init_states = (const int*)d_in[5];
    const float* W_out       = (const float*)d_in[6];
    const float* b_out       = (const float*)d_in[7];
    float* out = (float*)d_out;

    k_pre1<<<1032, 256>>>(x, w_in);                        // pack_x + pack_w
    k_pre2<<<1103, 256>>>(adj_list, adj_mask);             // build_u + pack_adj
    k_pre3<<<80079, 256>>>(lut, init_states);              // pack_lut (vec) + init

    cudaFuncSetAttribute(k_main, cudaFuncAttributeMaxDynamicSharedMemorySize, SLUT_BYTES);
    k_main<<<GRID_MAIN, TPB_MAIN, SLUT_BYTES>>>();         // 4th launch -> ncu capture
    k_readout<<<NBATCH, 256>>>(W_out, b_out, out);
}

// round 8
// speedup vs baseline: 2.8719x; 1.0680x over previous
#include <cuda_runtime.h>
#include <cuda_bf16.h>
#include <cstdint>

#define N_NODES   20000
#define N_INPUT   64
#define KMAX      12
#define NBITS     64
#define N_OUT     10
#define NBATCH    64
#define TSTEPS    128
#define LUTW      128         /* 4096 bits / 32 words */
#define DUMMY     20000
#define ST_SZ     20008
#define TPB_MAIN  1024
#define NPC       68          /* nodes per CTA (even) */
#define PAIRS     (NPC / 2)   /* 34 */
#define GRID_MAIN 294         /* 294*68 = 19992 >= 19936 ; 2 CTAs/SM */
#define SLUT_WORDS (NPC * LUTW)          /* 8704 words */
#define SLUT_BYTES (SLUT_WORDS * 4)      /* 34816 bytes -> 2 CTAs/SM fit easily */

// LUT bit layout (remapped for vectorized packing):
//   entry e -> word ((e>>7)<<2) | (e&3),  bit (e>>2)&31

// ---------------- device globals (scratch; no allocations allowed) ----------------
__device__ __align__(16) unsigned short g_adj[N_NODES * 16];   // lane-reversed packed adjacency
__device__ __align__(16) unsigned int g_lut[N_NODES * LUTW];   // 10.24 MB bit-packed LUT (remapped layout)
__device__ unsigned char g_non[N_NODES];                       // no-neighbor flag per node
__device__ uint2         g_st[2][ST_SZ];                       // bit-packed states; slot 20000 = always-0 dummy
__device__ uint2         g_u[TSTEPS * 64];                     // input-layer bits u[t][j]
__device__ uint2         g_xb[NBATCH * TSTEPS];                // packed x bits [b][t]
__device__ uint2         g_wc[64];                             // packed w_in columns
__device__ unsigned int  g_arrive;                             // MONOTONIC arrival counter

// ---------------- preprocessing (fused: 3 kernels) ----------------

// pre1: pack_x (blocks 0..1023) + pack_w (blocks 1024..1031)
__global__ void k_pre1(const int* __restrict__ x, const int* __restrict__ w_in) {
    int lane = threadIdx.x & 31;
    if (blockIdx.x < 1024) {
        int wid = (blockIdx.x * 256 + threadIdx.x) >> 5;   // 0..8191
        int b = wid >> 7, t = wid & 127;
        const int* p = x + ((size_t)b * TSTEPS + t) * NBITS;
        unsigned lo = __ballot_sync(0xffffffffu, p[lane] != 0);
        unsigned hi = __ballot_sync(0xffffffffu, p[lane + 32] != 0);
        if (lane == 0) g_xb[b * TSTEPS + t] = make_uint2(lo, hi);
    } else {
        int wid = ((blockIdx.x - 1024) * 256 + threadIdx.x) >> 5;  // 0..63
        unsigned lo = __ballot_sync(0xffffffffu, w_in[lane * 64 + wid] != 0);
        unsigned hi = __ballot_sync(0xffffffffu, w_in[(lane + 32) * 64 + wid] != 0);
        if (lane == 0) g_wc[wid] = make_uint2(lo, hi);
    }
}

// pre2: build_u (blocks 0..1023) + pack_adj (blocks 1024..1102)
__global__ void k_pre2(const int* __restrict__ adj_list, const int* __restrict__ adj_mask) {
    int lane = threadIdx.x & 31;
    if (blockIdx.x < 1024) {
        int wid = (blockIdx.x * 256 + threadIdx.x) >> 5;   // 0..8191
        int t = wid >> 6, j = wid & 63;
        uint2 wc = g_wc[j];
        uint2 xa = g_xb[lane * TSTEPS + t];
        uint2 xb = g_xb[(lane + 32) * TSTEPS + t];
        unsigned lo = __ballot_sync(0xffffffffu, ((xa.x & wc.x) | (xa.y & wc.y)) != 0);
        unsigned hi = __ballot_sync(0xffffffffu, ((xb.x & wc.x) | (xb.y & wc.y)) != 0);
        if (lane == 0) g_u[t * 64 + j] = make_uint2(lo, hi);
    } else {
        int n = (blockIdx.x - 1024) * 256 + threadIdx.x;
        if (n >= N_NODES) return;
        unsigned a[12];
        int any = 0;
#pragma unroll
        for (int k = 0; k < KMAX; k++) {
            int m = adj_mask[n * KMAX + k];
            any |= m;
            a[k] = m ? (unsigned)adj_list[n * KMAX + k] : (unsigned)DUMMY;
        }
        if (!any) {
#pragma unroll
            for (int k = 0; k < KMAX; k++) a[k] = DUMMY;
            a[11] = (unsigned)n;   // idx = old state bit (identity LUT)
        }
        g_non[n] = (unsigned char)(!any);
        unsigned r[16];
#pragma unroll
        for (int l = 0; l < 12; l++) r[l] = a[11 - l];     // lane-reversed
        r[12] = r[13] = r[14] = r[15] = DUMMY;
        uint4 v0, v1;
        v0.x = r[0]  | (r[1]  << 16); v0.y = r[2]  | (r[3]  << 16);
        v0.z = r[4]  | (r[5]  << 16); v0.w = r[6]  | (r[7]  << 16);
        v1.x = r[8]  | (r[9]  << 16); v1.y = r[10] | (r[11] << 16);
        v1.z = r[12] | (r[13] << 16); v1.w = r[14] | (r[15] << 16);
        ((uint4*)g_adj)[n * 2]     = v0;
        ((uint4*)g_adj)[n * 2 + 1] = v1;
    }
}

// pre3: pack_lut vectorized (blocks 0..79999) + state init (blocks 80000..80078).
// One warp per (node, 128-entry chunk): int4 load (16B/lane), 4 ballots -> 4 words,
// lane 0 stores uint4. Identity LUT for no-neighbor nodes: entry1 -> word1 bit0.
__global__ void k_pre3(const int* __restrict__ lut, const int* __restrict__ init_states) {
    if (blockIdx.x < 80000) {
        int gw   = blockIdx.x * 8 + (threadIdx.x >> 5);    // 0..639999
        int lane = threadIdx.x & 31;
        int node = gw >> 5, chunk = gw & 31;
        uint4 wout;
        if (g_non[node]) {
            wout = make_uint4(0u, (chunk == 0) ? 1u : 0u, 0u, 0u);
        } else {
            const int4* p = (const int4*)(lut + (size_t)node * 4096 + (size_t)chunk * 128);
            int4 v = p[lane];
            wout.x = __ballot_sync(0xffffffffu, v.x != 0);
            wout.y = __ballot_sync(0xffffffffu, v.y != 0);
            wout.z = __ballot_sync(0xffffffffu, v.z != 0);
            wout.w = __ballot_sync(0xffffffffu, v.w != 0);
        }
        if (lane == 0)
            ((uint4*)g_lut)[node * (LUTW / 4) + chunk] = wout;
    } else {
        int i = (blockIdx.x - 80000) * 256 + threadIdx.x;
        if (i == 0) g_arrive = 0;
        if (i >= ST_SZ) return;
        if (i < N_INPUT) {
            g_st[0][i] = g_u[i];                           // u[0][i]
        } else if (i < N_NODES) {
            int s = init_states[i];
            g_st[0][i] = s ? make_uint2(0xffffffffu, 0xffffffffu) : make_uint2(0u, 0u);
        } else {                                            // dummy + pad: zero both buffers
            g_st[0][i] = make_uint2(0u, 0u);
            g_st[1][i] = make_uint2(0u, 0u);
        }
    }
}

// ---------------- main persistent kernel ----------------

// 32x32 bit-matrix transpose distributed across a warp (5 butterfly stages).
__device__ __forceinline__ unsigned btrans32(unsigned x, int lane) {
    unsigned y;
    y = __shfl_xor_sync(0xffffffffu, x, 16);
    x = (lane & 16) ? ((x & 0xffff0000u) | ((y & 0xffff0000u) >> 16))
                    : ((x & 0x0000ffffu) | ((y & 0x0000ffffu) << 16));
    y = __shfl_xor_sync(0xffffffffu, x, 8);
    x = (lane & 8)  ? ((x & 0xff00ff00u) | ((y & 0xff00ff00u) >> 8))
                    : ((x & 0x00ff00ffu) | ((y & 0x00ff00ffu) << 8));
    y = __shfl_xor_sync(0xffffffffu, x, 4);
    x = (lane & 4)  ? ((x & 0xf0f0f0f0u) | ((y & 0xf0f0f0f0u) >> 4))
                    : ((x & 0x0f0f0f0fu) | ((y & 0x0f0f0f0fu) << 4));
    y = __shfl_xor_sync(0xffffffffu, x, 2);
    x = (lane & 2)  ? ((x & 0xccccccccu) | ((y & 0xccccccccu) >> 2))
                    : ((x & 0x33333333u) | ((y & 0x33333333u) << 2));
    y = __shfl_xor_sync(0xffffffffu, x, 1);
    x = (lane & 1)  ? ((x & 0xaaaaaaaau) | ((y & 0xaaaaaaaau) >> 1))
                    : ((x & 0x55555555u) | ((y & 0x55555555u) << 1));
    return x;
}

// remapped-layout LUT lookup: entry idx -> word ((idx>>7)<<2)|(idx&3), bit (idx>>2)&31
__device__ __forceinline__ unsigned lut_bit(const unsigned* __restrict__ row, unsigned idx) {
    unsigned wofs = ((idx >> 5) & ~3u) | (idx & 3u);
    return (row[wofs] >> ((idx >> 2) & 31u)) & 1u;
}

// Monotonic REDG barrier (validated): no-return atomicAdd + single-hop spin.
__device__ __forceinline__ void grid_bar(int t, int nblocks) {
    __syncthreads();
    if (threadIdx.x == 0) {
        __threadfence();                                   // release this CTA's state writes
        atomicAdd(&g_arrive, 1u);                          // return unused -> REDG
        const unsigned target = (unsigned)nblocks * (unsigned)(t + 1);
        while (*(volatile unsigned*)&g_arrive < target) { }
        __threadfence();                                   // acquire
    }
    __syncthreads();
}

__global__ void __launch_bounds__(TPB_MAIN, 2) k_main() {
    extern __shared__ unsigned s_lut[];                    // NPC * 128 words (34 KB)
    const int lane = threadIdx.x & 31;
    const int w    = threadIdx.x >> 5;                     // warp id in CTA (0..31)
    const int nb   = gridDim.x;
    const int start = N_INPUT + blockIdx.x * NPC;          // first node owned by this CTA

    // stage this CTA's LUT slice into shared memory (one-time)
    for (int i = threadIdx.x; i < SLUT_WORDS; i += TPB_MAIN) {
        int node = start + (i >> 7);
        s_lut[i] = (node < N_NODES) ? g_lut[node * LUTW + (i & 127)] : 0u;
    }

    // Pairing: pair p -> nodes (start+2p, start+2p+1). Warp w owns pairs
    // {w, w+32(<34)}. Lanes 0..11 hold A's lane-reversed adjacency,
    // lanes 16..27 hold B's; other lanes read the always-0 dummy.
    const bool laneA = (lane < KMAX);
    const bool laneB = (lane >= 16) && (lane < 16 + KMAX);
    const bool gath  = laneA || laneB;
    const int  niters = (w < PAIRS - 32) ? 2 : 1;          // 34 = 32 + 2

    unsigned adjreg[2];
#pragma unroll
    for (int i = 0; i < 2; i++) {
        int p = w + i * 32;
        unsigned ai = DUMMY;
        if (p < PAIRS) {
            int nA = start + 2 * p, nB = nA + 1;
            if (laneA && nA < N_NODES) ai = (unsigned)g_adj[nA * 16 + lane];
            if (laneB && nB < N_NODES) ai = (unsigned)g_adj[nB * 16 + (lane - 16)];
        }
        adjreg[i] = ai;
    }
    __syncthreads();                                       // s_lut ready

    int cur = 0;
    for (int t = 0; t < TSTEPS; t++) {
        const uint2* __restrict__ S = g_st[cur];
        uint2* __restrict__ D = g_st[cur ^ 1];

        // CTA 0 stages next step's input-layer bits into the destination buffer
        if (blockIdx.x == 0 && threadIdx.x < 64 && t + 1 < TSTEPS)
            D[threadIdx.x] = g_u[(t + 1) * 64 + threadIdx.x];

        // prefetch this warp's gathers before any compute (hide L2 latency)
        uint2 wv[2];
        wv[0] = wv[1] = make_uint2(0u, 0u);
        if (gath) {
            wv[0] = __ldcg(&S[adjreg[0]]);
            if (niters == 2) wv[1] = __ldcg(&S[adjreg[1]]);
        }

#pragma unroll
        for (int i = 0; i < 2; i++) {
            if (i >= niters) break;
            int p  = w + i * 32;
            int nA = start + 2 * p;
            int nB = nA + 1;
            unsigned tl = btrans32(wv[i].x, lane);          // [idxA | idxB<<16] batches 0-31
            unsigned th = btrans32(wv[i].y, lane);          // batches 32-63
            unsigned iAL = tl & 0xfffu, iBL = (tl >> 16) & 0xfffu;
            unsigned iAH = th & 0xfffu, iBH = (th >> 16) & 0xfffu;
            const unsigned* rowA = s_lut + (p << 8);        // local node 2p
            const unsigned* rowB = rowA + LUTW;             // local node 2p+1
            unsigned bAL = lut_bit(rowA, iAL);
            unsigned bAH = lut_bit(rowA, iAH);
            unsigned bBL = lut_bit(rowB, iBL);
            unsigned bBH = lut_bit(rowB, iBH);
            unsigned mAL = __ballot_sync(0xffffffffu, bAL);
            unsigned mAH = __ballot_sync(0xffffffffu, bAH);
            unsigned mBL = __ballot_sync(0xffffffffu, bBL);
            unsigned mBH = __ballot_sync(0xffffffffu, bBH);
            if (lane == 0 && nA < N_NODES) D[nA] = make_uint2(mAL, mAH);
            if (lane == 1 && nB < N_NODES) D[nB] = make_uint2(mBL, mBH);
        }

        grid_bar(t, nb);
        cur ^= 1;
    }
}

// ---------------- readout: sigmoid(states[:,64:] @ W^T + b) ----------------

__global__ void k_readout(const float* __restrict__ W, const float* __restrict__ bias,
                          float* __restrict__ out) {
    int b   = blockIdx.x;        // 64 blocks
    int tid = threadIdx.x;       // 256 threads
    int lane = tid & 31, wrp = tid >> 5;
    const uint2* __restrict__ S = g_st[0];   // TSTEPS even -> final states in buffer 0

    float acc[N_OUT];
#pragma unroll
    for (int o = 0; o < N_OUT; o++) acc[o] = 0.f;

    const int bsh = b & 31;
    for (int n = N_INPUT + tid; n < N_NODES; n += blockDim.x) {
        uint2 w = S[n];
        unsigned word = (b < 32) ? w.x : w.y;
        float bit = (float)((word >> bsh) & 1u);
        const float* wp = W + (n - N_INPUT);
#pragma unroll
        for (int o = 0; o < N_OUT; o++)
            acc[o] += bit * wp[o * (N_NODES - N_INPUT)];
    }

    __shared__ float part[8][N_OUT];
#pragma unroll
    for (int o = 0; o < N_OUT; o++) {
        float v = acc[o];
#pragma unroll
        for (int off = 16; off; off >>= 1) v += __shfl_down_sync(0xffffffffu, v, off);
        if (lane == 0) part[wrp][o] = v;
    }
    __syncthreads();
    if (tid < N_OUT) {
        float s = bias[tid];
#pragma unroll
        for (int w2 = 0; w2 < 8; w2++) s += part[w2][tid];
        out[b * N_OUT + tid] = 1.0f / (1.0f + expf(-s));
    }
}

// ---------------- launch ----------------

extern "C" void kernel_launch(void* const* d_in, const int* in_sizes, int n_in,
                              void* d_out, int out_size) {
    (void)in_sizes; (void)n_in; (void)out_size;
    const int*   x           = (const int*)d_in[0];
    const int*   w_in        = (const int*)d_in[1];
    const int*   adj_list    = (const int*)d_in[2];
    const int*   adj_mask    = (const int*)d_in[3];
    const int*   lut         = (const int*)d_in[4];
    const int*   init_states = (const int*)d_in[5];
    const float* W_out       = (const float*)d_in[6];
    const float* b_out       = (const float*)d_in[7];
    float* out = (float*)d_out;

    k_pre1<<<1032, 256>>>(x, w_in);                        // pack_x + pack_w
    k_pre2<<<1103, 256>>>(adj_list, adj_mask);             // build_u + pack_adj
    k_pre3<<<80079, 256>>>(lut, init_states);              // pack_lut (vec) + init

    cudaFuncSetAttribute(k_main, cudaFuncAttributeMaxDynamicSharedMemorySize, SLUT_BYTES);
    k_main<<<GRID_MAIN, TPB_MAIN, SLUT_BYTES>>>();         // 4th launch -> ncu capture
    k_readout<<<NBATCH, 256>>>(W_out, b_out, out);
}